// round 12
// baseline (speedup 1.0000x reference)
#include <cuda_runtime.h>
#include <math.h>

#define PP 65160              // H*W
#define HALF0 32592           // 1358 * 24
#define FULLM 0xffffffffu

typedef unsigned long long ull;

// scratch
__device__ float  g_xsT[PP * 32];
__device__ float2 g_xvT2[PP * 16];
__device__ float4 g_Z4[144 * PP];   // z features, [fq][p] float4 (k-packed)

__device__ __forceinline__ float gelu_exact(float x) { return x * normcdff(x); }

__device__ __forceinline__ ull pack2(float x, float y) {
    ull r; asm("mov.b64 %0,{%1,%2};" : "=l"(r) : "f"(x), "f"(y)); return r;
}
__device__ __forceinline__ void fma2(ull& d, ull a, ull b) {
    asm("fma.rn.f32x2 %0,%1,%2,%0;" : "+l"(d) : "l"(a), "l"(b));
}
__device__ __forceinline__ float2 unpk(ull v) {
    float2 r; asm("mov.b64 {%0,%1},%2;" : "=f"(r.x), "=f"(r.y) : "l"(v)); return r;
}

// -------------------------------------------------------------------------
// Transpose x_scalar (32,P)->(P,32) and x_vector (16,P,2)->(P,16) float2
// -------------------------------------------------------------------------
__global__ void transpose_x(const float* __restrict__ xs,
                            const float* __restrict__ xv) {
    const int p0 = blockIdx.x * 32;
    const int tx = threadIdx.x;   // 32
    const int ty = threadIdx.y;   // 8
    if (blockIdx.y == 0) {
        __shared__ float tile[32][33];
        #pragma unroll
        for (int r = ty; r < 32; r += 8) {
            int pp = p0 + tx;
            tile[r][tx] = (pp < PP) ? xs[r * PP + pp] : 0.f;
        }
        __syncthreads();
        #pragma unroll
        for (int r = ty; r < 32; r += 8) {
            int pp = p0 + r;
            if (pp < PP) g_xsT[pp * 32 + tx] = tile[tx][r];
        }
    } else {
        __shared__ float2 t2[16][33];
        const float2* xv2 = (const float2*)xv;
        #pragma unroll
        for (int r = ty; r < 16; r += 8) {
            int pp = p0 + tx;
            t2[r][tx] = (pp < PP) ? xv2[r * PP + pp] : make_float2(0.f, 0.f);
        }
        __syncthreads();
        const int tid = ty * 32 + tx;
        #pragma unroll
        for (int q = tid; q < 512; q += 256) {
            int i = q >> 4, v = q & 15;
            int pp = p0 + i;
            if (pp < PP) g_xvT2[pp * 16 + v] = t2[v][i];
        }
    }
}

// profile-window steering: position-4 launch in the graph gets captured
__global__ void prof_marker() {}

// -------------------------------------------------------------------------
// Kernel A (R10 body + point offset): z producer. Raw-psi staging (5
// STS.128), conflict-free tile ([pl][fq] stride 145 f4), chunked gathers.
// 8 warps x 3 points = 24 pts/block.
// fq map: 0..31 zss(i), 32..47 zvs(i), 48..79 zsv(c0,i), 80..111 zsv(c1,i),
//         112..127 zvv(c0,i), 128..143 zvv(c1,i)
// -------------------------------------------------------------------------
#define A_ZONE_OFF 13920                       // floats (tile = 3480 f4)
#define A_SMEM_FLOATS (13920 + 8 * 576)        // 18528
#define A_SMEM_BYTES (A_SMEM_FLOATS * 4)       // 74112

__global__ void __launch_bounds__(256, 2)
disco_z(int pofs, const int* __restrict__ idx,
        const float* __restrict__ psi_ss, const float* __restrict__ psi_sv,
        const float* __restrict__ psi_vs, const float* __restrict__ psi_vv) {
    extern __shared__ float sm[];
    float4* T4 = (float4*)sm;
    const int tid  = threadIdx.x;
    const int warp = tid >> 5;
    const int lane = tid & 31;
    const int h    = lane >> 4;       // c / k-pair selector
    const int ch   = lane & 15;       // vector channel
    float* zone = sm + A_ZONE_OFF + warp * 576;

    const float4* gss = (const float4*)psi_ss;
    const float4* gsv = (const float4*)psi_sv;
    const float4* gvs = (const float4*)psi_vs;
    const float4* gvv = (const float4*)psi_vv;

    const int pbase = pofs + blockIdx.x * 24 + warp * 3;

    #pragma unroll 1
    for (int q = 0; q < 3; q++) {
        const int p  = pbase + q;
        const int pl = warp * 3 + q;

        int jreg = (lane < 16) ? idx[p * 16 + lane] : 0;

        // ---- load psi raw (registers) ----
        float4 fss;
        if (lane < 16) fss = gss[((lane >> 2) * PP + p) * 4 + (lane & 3)];
        float4 fsv = gsv[((lane >> 3) * PP + p) * 8 + (lane & 7)];
        float4 fvs = gvs[((lane >> 3) * PP + p) * 8 + (lane & 7)];
        float4 fv0 = gvv[(h * PP + p) * 16 + ch];
        float4 fv1 = gvv[((h + 2) * PP + p) * 16 + ch];

        // ---- stage psi (raw; only psi_vv split by c) ----
        if (lane < 16) ((float4*)zone)[lane] = fss;
        ((float4*)(zone + 64))[lane]  = fsv;
        ((float4*)(zone + 192))[lane] = fvs;
        {
            ull* pc0 = (ull*)(zone + 320);
            ull* pc1 = (ull*)(zone + 448);
            pc0[h * 16 + ch]       = pack2(fv0.x, fv0.y);   // c0, d-pair
            pc1[h * 16 + ch]       = pack2(fv0.z, fv0.w);   // c1, d-pair
            pc0[(h + 2) * 16 + ch] = pack2(fv1.x, fv1.y);
            pc1[(h + 2) * 16 + ch] = pack2(fv1.z, fv1.w);
        }
        __syncwarp();

        const ull* PssU = (const ull*)zone;                 // [k*8 + npair]
        const ull* PsvU = (const ull*)(zone + 64);          // [k*16 + n] = (c0,c1)
        const ull* PvsU = (const ull*)(zone + 192);         // [k*16 + n] = (c0,c1)
        const ull* PvvU = (const ull*)(zone + 320) + h * 64;// [k*16 + n] = (d0,d1), c=h

        ull zss[4] = {0,0,0,0};
        ull zsv[4] = {0,0,0,0};
        ull zvs0 = 0, zvs1 = 0;
        ull zvv[4] = {0,0,0,0};

        // ---- gather + accumulate in 2 chunks of 8 neighbors ----
        #pragma unroll
        for (int cH = 0; cH < 2; cH++) {
            float  xsg[8];
            float2 xvg[8];
            #pragma unroll
            for (int n8 = 0; n8 < 8; n8++) {
                int jn = __shfl_sync(FULLM, jreg, cH * 8 + n8);
                xsg[n8] = g_xsT[jn * 32 + lane];
                xvg[n8] = g_xvT2[jn * 16 + ch];
            }
            #pragma unroll
            for (int m = 0; m < 4; m++) {
                ull xp = pack2(xsg[2 * m], xsg[2 * m + 1]);
                int pr = cH * 4 + m;
                fma2(zss[0], PssU[pr],      xp);
                fma2(zss[1], PssU[8 + pr],  xp);
                fma2(zss[2], PssU[16 + pr], xp);
                fma2(zss[3], PssU[24 + pr], xp);
            }
            #pragma unroll
            for (int n8 = 0; n8 < 8; n8++) {
                int n = cH * 8 + n8;
                ull xs2 = pack2(xsg[n8], xsg[n8]);
                fma2(zsv[0], PsvU[n],      xs2);
                fma2(zsv[1], PsvU[16 + n], xs2);
                fma2(zsv[2], PsvU[32 + n], xs2);
                fma2(zsv[3], PsvU[48 + n], xs2);
                ull xvp = pack2(xvg[n8].x, xvg[n8].y);
                fma2(zvs0, PvsU[(2 * h) * 16 + n],     xvp);
                fma2(zvs1, PvsU[(2 * h + 1) * 16 + n], xvp);
                fma2(zvv[0], PvvU[n],      xvp);
                fma2(zvv[1], PvvU[16 + n], xvp);
                fma2(zvv[2], PvvU[32 + n], xvp);
                fma2(zvv[3], PvvU[48 + n], xvp);
            }
        }

        // ---- reduce + conflict-free tile stores ----
        float4* Trow = T4 + pl * 145;
        {
            float2 a0 = unpk(zss[0]), a1 = unpk(zss[1]);
            float2 a2 = unpk(zss[2]), a3 = unpk(zss[3]);
            Trow[lane] = make_float4(a0.x + a0.y, a1.x + a1.y, a2.x + a2.y, a3.x + a3.y);
        }
        {
            float2 a0 = unpk(zsv[0]), a1 = unpk(zsv[1]);
            float2 a2 = unpk(zsv[2]), a3 = unpk(zsv[3]);
            Trow[48 + lane] = make_float4(a0.x, a1.x, a2.x, a3.x);   // c0
            Trow[80 + lane] = make_float4(a0.y, a1.y, a2.y, a3.y);   // c1
        }
        {
            float2 a0 = unpk(zvs0), a1 = unpk(zvs1);
            ((ull*)&Trow[32 + ch])[h] = pack2(a0.x + a0.y, a1.x + a1.y);
        }
        {
            float2 a0 = unpk(zvv[0]), a1 = unpk(zvv[1]);
            float2 a2 = unpk(zvv[2]), a3 = unpk(zvv[3]);
            Trow[112 + lane] = make_float4(a0.x + a0.y, a1.x + a1.y, a2.x + a2.y, a3.x + a3.y);
        }
        __syncwarp();
    }

    // ---- coalesced tile -> global (smem reads conflict-free: odd stride) ----
    __syncthreads();
    const int p0 = pofs + blockIdx.x * 24;
    #pragma unroll 1
    for (int t = tid; t < 144 * 24; t += 256) {
        int fq = t / 24, pl = t % 24;
        g_Z4[fq * PP + p0 + pl] = T4[pl * 145 + fq];
    }
}

// -------------------------------------------------------------------------
// Kernel B: GEMM chain with o-paired f32x2. lane = point, per-half launch.
// -------------------------------------------------------------------------
#define B_BIAS 13824
#define B_SMEM_BYTES (13968 * 4)

__global__ void __launch_bounds__(256, 2)
disco_w(int pstart, int pend,
        const float* __restrict__ xs, const float* __restrict__ xv,
        const float* __restrict__ W_ss, const float* __restrict__ W_vs,
        const float* __restrict__ W_sv, const float* __restrict__ W_vv,
        const float* __restrict__ bias_s,
        const float* __restrict__ mlp_w1, const float* __restrict__ mlp_b1,
        const float* __restrict__ mlp_w2, const float* __restrict__ mlp_b2,
        const float* __restrict__ gate_w, const float* __restrict__ gate_b,
        float* __restrict__ out) {
    extern __shared__ float sm[];
    const int tid = threadIdx.x;

    // ---- stage W into [..][o]-contiguous layouts ----
    {
        const float4* g = (const float4*)W_ss;
        for (int t = tid; t < 1024; t += 256) { int o = t >> 5, i = t & 31; float4 f = g[t];
            float* b = sm + (i * 4) * 32 + o; b[0] = f.x; b[32] = f.y; b[64] = f.z; b[96] = f.w; }
        g = (const float4*)W_vs;
        for (int t = tid; t < 512; t += 256) { int o = t >> 4, i = t & 15; float4 f = g[t];
            float* b = sm + ((32 + i) * 4) * 32 + o; b[0] = f.x; b[32] = f.y; b[64] = f.z; b[96] = f.w; }
        g = (const float4*)W_sv;
        for (int t = tid; t < 512; t += 256) { int o = t >> 5, i = t & 31; float4 f = g[t];
            float* b = sm + 6144 + (i * 4) * 16 + o; b[0] = f.x; b[16] = f.y; b[32] = f.z; b[48] = f.w; }
        g = (const float4*)W_vv;
        for (int t = tid; t < 256; t += 256) { int o = t >> 4, i = t & 15; float4 f = g[t];
            float* b = sm + 6144 + ((32 + i) * 4) * 16 + o; b[0] = f.x; b[16] = f.y; b[32] = f.z; b[48] = f.w; }
        g = (const float4*)mlp_w1;
        for (int t = tid; t < 512; t += 256) { int j = t >> 3, i4 = t & 7; float4 f = g[t];
            float* b = sm + 9216 + (i4 * 4) * 64 + j; b[0] = f.x; b[64] = f.y; b[128] = f.z; b[192] = f.w; }
        g = (const float4*)mlp_w2;
        for (int t = tid; t < 512; t += 256) { int o = t >> 4, j4 = t & 15; float4 f = g[t];
            float* b = sm + 11264 + (j4 * 4) * 32 + o; b[0] = f.x; b[32] = f.y; b[64] = f.z; b[96] = f.w; }
        g = (const float4*)gate_w;
        for (int t = tid; t < 128; t += 256) { int v = t >> 3, i4 = t & 7; float4 f = g[t];
            float* b = sm + 13312 + (i4 * 4) * 16 + v; b[0] = f.x; b[16] = f.y; b[32] = f.z; b[48] = f.w; }
        if (tid < 32) sm[B_BIAS + tid]       = bias_s[tid];
        if (tid < 64) sm[B_BIAS + 32 + tid]  = mlp_b1[tid];
        if (tid < 32) sm[B_BIAS + 96 + tid]  = mlp_b2[tid];
        if (tid < 16) sm[B_BIAS + 128 + tid] = gate_b[tid];
    }
    __syncthreads();

    const int p  = pstart + blockIdx.x * 256 + tid;
    const int pc = (p < pend) ? p : (pend - 1);

    // ---- phase S: acc (o-pairs) ----
    ull acc[16];
    #pragma unroll
    for (int qq = 0; qq < 16; qq++) acc[qq] = *(const ull*)(sm + B_BIAS + 2 * qq);
    #pragma unroll 2
    for (int r = 0; r < 48; r++) {
        float4 z = g_Z4[r * PP + pc];
        ull zk0 = pack2(z.x, z.x), zk1 = pack2(z.y, z.y);
        ull zk2 = pack2(z.z, z.z), zk3 = pack2(z.w, z.w);
        const ulonglong2* w0 = (const ulonglong2*)(sm + r * 128);
        #pragma unroll
        for (int q2 = 0; q2 < 8; q2++) {
            ulonglong2 a = w0[q2], b = w0[8 + q2], c = w0[16 + q2], d = w0[24 + q2];
            fma2(acc[2*q2],   a.x, zk0); fma2(acc[2*q2+1], a.y, zk0);
            fma2(acc[2*q2],   b.x, zk1); fma2(acc[2*q2+1], b.y, zk1);
            fma2(acc[2*q2],   c.x, zk2); fma2(acc[2*q2+1], c.y, zk2);
            fma2(acc[2*q2],   d.x, zk3); fma2(acc[2*q2+1], d.y, zk3);
        }
    }
    float s[32];
    #pragma unroll
    for (int qq = 0; qq < 16; qq++) {
        float2 u = unpk(acc[qq]);
        s[2*qq] = gelu_exact(u.x); s[2*qq+1] = gelu_exact(u.y);
    }

    // ---- MLP (j-quarters) ----
    ull soa[16];
    #pragma unroll
    for (int qq = 0; qq < 16; qq++)
        soa[qq] = pack2(s[2*qq] + sm[B_BIAS + 96 + 2*qq], s[2*qq+1] + sm[B_BIAS + 97 + 2*qq]);
    #pragma unroll 1
    for (int qt = 0; qt < 4; qt++) {
        ull ha[8];
        #pragma unroll
        for (int qq = 0; qq < 8; qq++) ha[qq] = *(const ull*)(sm + B_BIAS + 32 + qt * 16 + 2 * qq);
        #pragma unroll
        for (int i = 0; i < 32; i++) {
            ull sx = pack2(s[i], s[i]);
            const ulonglong2* w1r = (const ulonglong2*)(sm + 9216 + i * 64 + qt * 16);
            #pragma unroll
            for (int q2 = 0; q2 < 4; q2++) {
                ulonglong2 ww = w1r[q2];
                fma2(ha[2*q2], ww.x, sx); fma2(ha[2*q2+1], ww.y, sx);
            }
        }
        float hh[16];
        #pragma unroll
        for (int qq = 0; qq < 8; qq++) {
            float2 u = unpk(ha[qq]);
            hh[2*qq] = gelu_exact(u.x); hh[2*qq+1] = gelu_exact(u.y);
        }
        #pragma unroll
        for (int jj = 0; jj < 16; jj++) {
            int j = qt * 16 + jj;
            ull hx = pack2(hh[jj], hh[jj]);
            const ulonglong2* w2r = (const ulonglong2*)(sm + 11264 + j * 32);
            #pragma unroll
            for (int q2 = 0; q2 < 8; q2++) {
                ulonglong2 ww = w2r[q2];
                fma2(soa[2*q2], ww.x, hx); fma2(soa[2*q2+1], ww.y, hx);
            }
        }
    }
    float so[32];
    #pragma unroll
    for (int qq = 0; qq < 16; qq++) { float2 u = unpk(soa[qq]); so[2*qq] = u.x; so[2*qq+1] = u.y; }

    // ---- gate ----
    ull ga[8];
    #pragma unroll
    for (int qq = 0; qq < 8; qq++) ga[qq] = *(const ull*)(sm + B_BIAS + 128 + 2 * qq);
    #pragma unroll
    for (int i = 0; i < 32; i++) {
        ull sx = pack2(so[i], so[i]);
        const ulonglong2* gr = (const ulonglong2*)(sm + 13312 + i * 16);
        #pragma unroll
        for (int q2 = 0; q2 < 4; q2++) {
            ulonglong2 ww = gr[q2];
            fma2(ga[2*q2], ww.x, sx); fma2(ga[2*q2+1], ww.y, sx);
        }
    }
    float gte[16];
    #pragma unroll
    for (int qq = 0; qq < 8; qq++) { float2 u = unpk(ga[qq]); gte[2*qq] = 1.f + u.x; gte[2*qq+1] = 1.f + u.y; }

    // ---- scalar output ----
    if (p < pend) {
        #pragma unroll
        for (int o = 0; o < 32; o++) out[o * PP + p] = xs[o * PP + p] + so[o];
    }

    // ---- phase V (o-pairs; vx = c0, vy = c1) ----
    ull vx[8], vy[8];
    #pragma unroll
    for (int qq = 0; qq < 8; qq++) { vx[qq] = 0ULL; vy[qq] = 0ULL; }
    #pragma unroll 2
    for (int r = 0; r < 32; r++) {
        float4 z0 = g_Z4[(48 + r) * PP + pc];
        float4 z1 = g_Z4[(80 + r) * PP + pc];
        ull a0 = pack2(z0.x, z0.x), a1 = pack2(z0.y, z0.y), a2 = pack2(z0.z, z0.z), a3 = pack2(z0.w, z0.w);
        ull b0 = pack2(z1.x, z1.x), b1 = pack2(z1.y, z1.y), b2 = pack2(z1.z, z1.z), b3 = pack2(z1.w, z1.w);
        const ulonglong2* wv = (const ulonglong2*)(sm + 6144 + r * 64);
        #pragma unroll
        for (int q2 = 0; q2 < 4; q2++) {
            ulonglong2 wa = wv[q2], wb = wv[4 + q2], wc = wv[8 + q2], wd = wv[12 + q2];
            fma2(vx[2*q2], wa.x, a0); fma2(vx[2*q2+1], wa.y, a0);
            fma2(vy[2*q2], wa.x, b0); fma2(vy[2*q2+1], wa.y, b0);
            fma2(vx[2*q2], wb.x, a1); fma2(vx[2*q2+1], wb.y, a1);
            fma2(vy[2*q2], wb.x, b1); fma2(vy[2*q2+1], wb.y, b1);
            fma2(vx[2*q2], wc.x, a2); fma2(vx[2*q2+1], wc.y, a2);
            fma2(vy[2*q2], wc.x, b2); fma2(vy[2*q2+1], wc.y, b2);
            fma2(vx[2*q2], wd.x, a3); fma2(vx[2*q2+1], wd.y, a3);
            fma2(vy[2*q2], wd.x, b3); fma2(vy[2*q2+1], wd.y, b3);
        }
    }
    #pragma unroll 2
    for (int r = 0; r < 16; r++) {
        float4 z0 = g_Z4[(112 + r) * PP + pc];
        float4 z1 = g_Z4[(128 + r) * PP + pc];
        ull a0 = pack2(z0.x, z0.x), a1 = pack2(z0.y, z0.y), a2 = pack2(z0.z, z0.z), a3 = pack2(z0.w, z0.w);
        ull b0 = pack2(z1.x, z1.x), b1 = pack2(z1.y, z1.y), b2 = pack2(z1.z, z1.z), b3 = pack2(z1.w, z1.w);
        const ulonglong2* wv = (const ulonglong2*)(sm + 6144 + (32 + r) * 64);
        #pragma unroll
        for (int q2 = 0; q2 < 4; q2++) {
            ulonglong2 wa = wv[q2], wb = wv[4 + q2], wc = wv[8 + q2], wd = wv[12 + q2];
            fma2(vx[2*q2], wa.x, a0); fma2(vx[2*q2+1], wa.y, a0);
            fma2(vy[2*q2], wa.x, b0); fma2(vy[2*q2+1], wa.y, b0);
            fma2(vx[2*q2], wb.x, a1); fma2(vx[2*q2+1], wb.y, a1);
            fma2(vy[2*q2], wb.x, b1); fma2(vy[2*q2+1], wb.y, b1);
            fma2(vx[2*q2], wc.x, a2); fma2(vx[2*q2+1], wc.y, a2);
            fma2(vy[2*q2], wc.x, b2); fma2(vy[2*q2+1], wc.y, b2);
            fma2(vx[2*q2], wd.x, a3); fma2(vx[2*q2+1], wd.y, a3);
            fma2(vy[2*q2], wd.x, b3); fma2(vy[2*q2+1], wd.y, b3);
        }
    }
    if (p < pend) {
        const float2* xv2g = (const float2*)xv;
        float2* outv = (float2*)(out + 32 * PP);
        #pragma unroll
        for (int qq = 0; qq < 8; qq++) {
            float2 ux = unpk(vx[qq]), uy = unpk(vy[qq]);
            int o0 = 2 * qq, o1 = 2 * qq + 1;
            float2 b0 = xv2g[o0 * PP + p], b1 = xv2g[o1 * PP + p];
            outv[o0 * PP + p] = make_float2(b0.x + ux.x * gte[o0], b0.y + uy.x * gte[o0]);
            outv[o1 * PP + p] = make_float2(b1.x + ux.y * gte[o1], b1.y + uy.y * gte[o1]);
        }
    }
}

extern "C" void kernel_launch(void* const* d_in, const int* in_sizes, int n_in,
                              void* d_out, int out_size) {
    const bool dictOrder = (in_sizes[2] == PP * 16);
    const float* xs = (const float*)d_in[0];
    const float* xv = (const float*)d_in[1];
    const int base = dictOrder ? 3 : 2;
    const float* pss  = (const float*)d_in[base + 0];
    const float* psv  = (const float*)d_in[base + 1];
    const float* pvs  = (const float*)d_in[base + 2];
    const float* pvv  = (const float*)d_in[base + 3];
    const float* wss  = (const float*)d_in[base + 4];
    const float* wvs  = (const float*)d_in[base + 5];
    const float* wsv  = (const float*)d_in[base + 6];
    const float* wvv  = (const float*)d_in[base + 7];
    const float* bs   = (const float*)d_in[base + 8];
    const float* w1   = (const float*)d_in[base + 9];
    const float* b1   = (const float*)d_in[base + 10];
    const float* w2   = (const float*)d_in[base + 11];
    const float* b2   = (const float*)d_in[base + 12];
    const float* gw   = (const float*)d_in[base + 13];
    const float* gb   = (const float*)d_in[base + 14];
    const int*   idx  = (const int*)(dictOrder ? d_in[2] : d_in[17]);

    cudaFuncSetAttribute(disco_z, cudaFuncAttributeMaxDynamicSharedMemorySize, A_SMEM_BYTES);
    cudaFuncSetAttribute(disco_w, cudaFuncAttributeMaxDynamicSharedMemorySize, B_SMEM_BYTES);

    float* out = (float*)d_out;
    dim3 tb(32, 8);
    // Phase-split halves so each half's Z (~75 MB) stays L2-resident between
    // its producer and consumer. Position 4 = disco_w(h0) gets profiled.
    transpose_x<<<dim3((PP + 31) / 32, 2), tb>>>(xs, xv);
    disco_z<<<1358, 256, A_SMEM_BYTES>>>(0, idx, pss, psv, pvs, pvv);
    prof_marker<<<1, 32>>>();
    disco_w<<<128, 256, B_SMEM_BYTES>>>(0, HALF0, xs, xv, wss, wvs, wsv, wvv, bs,
                                        w1, b1, w2, b2, gw, gb, out);
    disco_z<<<1357, 256, A_SMEM_BYTES>>>(HALF0, idx, pss, psv, pvs, pvv);
    disco_w<<<128, 256, B_SMEM_BYTES>>>(HALF0, PP, xs, xv, wss, wvs, wsv, wvv, bs,
                                        w1, b1, w2, b2, gw, gb, out);
}

// round 13
// speedup vs baseline: 1.1837x; 1.1837x over previous
#include <cuda_runtime.h>
#include <math.h>

#define PP 65160              // H*W
#define FULLM 0xffffffffu

typedef unsigned long long ull;

// scratch
__device__ float  g_xsT[PP * 32];
__device__ float2 g_xvT2[PP * 16];
__device__ float4 g_Z4[144 * PP];   // z features, [fq][p] float4 (k-packed)
__device__ float  g_gte[16 * PP];   // gate (1+g), [v][p]

__device__ __forceinline__ float gelu_exact(float x) { return x * normcdff(x); }

__device__ __forceinline__ ull pack2(float x, float y) {
    ull r; asm("mov.b64 %0,{%1,%2};" : "=l"(r) : "f"(x), "f"(y)); return r;
}
__device__ __forceinline__ void fma2(ull& d, ull a, ull b) {
    asm("fma.rn.f32x2 %0,%1,%2,%0;" : "+l"(d) : "l"(a), "l"(b));
}
__device__ __forceinline__ float2 unpk(ull v) {
    float2 r; asm("mov.b64 {%0,%1},%2;" : "=f"(r.x), "=f"(r.y) : "l"(v)); return r;
}

// -------------------------------------------------------------------------
// Transpose x_scalar (32,P)->(P,32) and x_vector (16,P,2)->(P,16) float2
// -------------------------------------------------------------------------
__global__ void transpose_x(const float* __restrict__ xs,
                            const float* __restrict__ xv) {
    const int p0 = blockIdx.x * 32;
    const int tx = threadIdx.x;   // 32
    const int ty = threadIdx.y;   // 8
    if (blockIdx.y == 0) {
        __shared__ float tile[32][33];
        #pragma unroll
        for (int r = ty; r < 32; r += 8) {
            int pp = p0 + tx;
            tile[r][tx] = (pp < PP) ? xs[r * PP + pp] : 0.f;
        }
        __syncthreads();
        #pragma unroll
        for (int r = ty; r < 32; r += 8) {
            int pp = p0 + r;
            if (pp < PP) g_xsT[pp * 32 + tx] = tile[tx][r];
        }
    } else {
        __shared__ float2 t2[16][33];
        const float2* xv2 = (const float2*)xv;
        #pragma unroll
        for (int r = ty; r < 16; r += 8) {
            int pp = p0 + tx;
            t2[r][tx] = (pp < PP) ? xv2[r * PP + pp] : make_float2(0.f, 0.f);
        }
        __syncthreads();
        const int tid = ty * 32 + tx;
        #pragma unroll
        for (int q = tid; q < 512; q += 256) {
            int i = q >> 4, v = q & 15;
            int pp = p0 + i;
            if (pp < PP) g_xvT2[pp * 16 + v] = t2[v][i];
        }
    }
}

// -------------------------------------------------------------------------
// Kernel A (R10 body): z producer. Raw-psi staging, conflict-free tile
// ([pl][fq] stride 145 f4), chunked gathers. 8 warps x 3 pts, 2715 blocks.
// fq map: 0..31 zss(i), 32..47 zvs(i), 48..79 zsv(c0,i), 80..111 zsv(c1,i),
//         112..127 zvv(c0,i), 128..143 zvv(c1,i)
// -------------------------------------------------------------------------
#define A_ZONE_OFF 13920                       // floats (tile = 3480 f4)
#define A_SMEM_FLOATS (13920 + 8 * 576)        // 18528
#define A_SMEM_BYTES (A_SMEM_FLOATS * 4)       // 74112

__global__ void __launch_bounds__(256, 2)
disco_z(const int* __restrict__ idx,
        const float* __restrict__ psi_ss, const float* __restrict__ psi_sv,
        const float* __restrict__ psi_vs, const float* __restrict__ psi_vv) {
    extern __shared__ float sm[];
    float4* T4 = (float4*)sm;
    const int tid  = threadIdx.x;
    const int warp = tid >> 5;
    const int lane = tid & 31;
    const int h    = lane >> 4;       // c / k-pair selector
    const int ch   = lane & 15;       // vector channel
    float* zone = sm + A_ZONE_OFF + warp * 576;

    const float4* gss = (const float4*)psi_ss;
    const float4* gsv = (const float4*)psi_sv;
    const float4* gvs = (const float4*)psi_vs;
    const float4* gvv = (const float4*)psi_vv;

    const int pbase = blockIdx.x * 24 + warp * 3;

    #pragma unroll 1
    for (int q = 0; q < 3; q++) {
        const int p  = pbase + q;
        const int pl = warp * 3 + q;

        int jreg = (lane < 16) ? idx[p * 16 + lane] : 0;

        // ---- load psi raw (registers) ----
        float4 fss;
        if (lane < 16) fss = gss[((lane >> 2) * PP + p) * 4 + (lane & 3)];
        float4 fsv = gsv[((lane >> 3) * PP + p) * 8 + (lane & 7)];
        float4 fvs = gvs[((lane >> 3) * PP + p) * 8 + (lane & 7)];
        float4 fv0 = gvv[(h * PP + p) * 16 + ch];
        float4 fv1 = gvv[((h + 2) * PP + p) * 16 + ch];

        // ---- stage psi (raw; only psi_vv split by c) ----
        if (lane < 16) ((float4*)zone)[lane] = fss;
        ((float4*)(zone + 64))[lane]  = fsv;
        ((float4*)(zone + 192))[lane] = fvs;
        {
            ull* pc0 = (ull*)(zone + 320);
            ull* pc1 = (ull*)(zone + 448);
            pc0[h * 16 + ch]       = pack2(fv0.x, fv0.y);   // c0, d-pair
            pc1[h * 16 + ch]       = pack2(fv0.z, fv0.w);   // c1, d-pair
            pc0[(h + 2) * 16 + ch] = pack2(fv1.x, fv1.y);
            pc1[(h + 2) * 16 + ch] = pack2(fv1.z, fv1.w);
        }
        __syncwarp();

        const ull* PssU = (const ull*)zone;                 // [k*8 + npair]
        const ull* PsvU = (const ull*)(zone + 64);          // [k*16 + n] = (c0,c1)
        const ull* PvsU = (const ull*)(zone + 192);         // [k*16 + n] = (c0,c1)
        const ull* PvvU = (const ull*)(zone + 320) + h * 64;// [k*16 + n] = (d0,d1), c=h

        ull zss[4] = {0,0,0,0};
        ull zsv[4] = {0,0,0,0};
        ull zvs0 = 0, zvs1 = 0;
        ull zvv[4] = {0,0,0,0};

        // ---- gather + accumulate in 2 chunks of 8 neighbors ----
        #pragma unroll
        for (int cH = 0; cH < 2; cH++) {
            float  xsg[8];
            float2 xvg[8];
            #pragma unroll
            for (int n8 = 0; n8 < 8; n8++) {
                int jn = __shfl_sync(FULLM, jreg, cH * 8 + n8);
                xsg[n8] = g_xsT[jn * 32 + lane];
                xvg[n8] = g_xvT2[jn * 16 + ch];
            }
            #pragma unroll
            for (int m = 0; m < 4; m++) {
                ull xp = pack2(xsg[2 * m], xsg[2 * m + 1]);
                int pr = cH * 4 + m;
                fma2(zss[0], PssU[pr],      xp);
                fma2(zss[1], PssU[8 + pr],  xp);
                fma2(zss[2], PssU[16 + pr], xp);
                fma2(zss[3], PssU[24 + pr], xp);
            }
            #pragma unroll
            for (int n8 = 0; n8 < 8; n8++) {
                int n = cH * 8 + n8;
                ull xs2 = pack2(xsg[n8], xsg[n8]);
                fma2(zsv[0], PsvU[n],      xs2);
                fma2(zsv[1], PsvU[16 + n], xs2);
                fma2(zsv[2], PsvU[32 + n], xs2);
                fma2(zsv[3], PsvU[48 + n], xs2);
                ull xvp = pack2(xvg[n8].x, xvg[n8].y);
                fma2(zvs0, PvsU[(2 * h) * 16 + n],     xvp);
                fma2(zvs1, PvsU[(2 * h + 1) * 16 + n], xvp);
                fma2(zvv[0], PvvU[n],      xvp);
                fma2(zvv[1], PvvU[16 + n], xvp);
                fma2(zvv[2], PvvU[32 + n], xvp);
                fma2(zvv[3], PvvU[48 + n], xvp);
            }
        }

        // ---- reduce + conflict-free tile stores ----
        float4* Trow = T4 + pl * 145;
        {
            float2 a0 = unpk(zss[0]), a1 = unpk(zss[1]);
            float2 a2 = unpk(zss[2]), a3 = unpk(zss[3]);
            Trow[lane] = make_float4(a0.x + a0.y, a1.x + a1.y, a2.x + a2.y, a3.x + a3.y);
        }
        {
            float2 a0 = unpk(zsv[0]), a1 = unpk(zsv[1]);
            float2 a2 = unpk(zsv[2]), a3 = unpk(zsv[3]);
            Trow[48 + lane] = make_float4(a0.x, a1.x, a2.x, a3.x);   // c0
            Trow[80 + lane] = make_float4(a0.y, a1.y, a2.y, a3.y);   // c1
        }
        {
            float2 a0 = unpk(zvs0), a1 = unpk(zvs1);
            ((ull*)&Trow[32 + ch])[h] = pack2(a0.x + a0.y, a1.x + a1.y);
        }
        {
            float2 a0 = unpk(zvv[0]), a1 = unpk(zvv[1]);
            float2 a2 = unpk(zvv[2]), a3 = unpk(zvv[3]);
            Trow[112 + lane] = make_float4(a0.x + a0.y, a1.x + a1.y, a2.x + a2.y, a3.x + a3.y);
        }
        __syncwarp();
    }

    // ---- coalesced tile -> global (smem reads conflict-free: odd stride) ----
    __syncthreads();
    const int p0 = blockIdx.x * 24;
    #pragma unroll 1
    for (int t = tid; t < 144 * 24; t += 256) {
        int fq = t / 24, pl = t % 24;
        g_Z4[fq * PP + p0 + pl] = T4[pl * 145 + fq];
    }
}

// -------------------------------------------------------------------------
// Kernel B1: scalar path (S-contraction, MLP, gate). Writes scalar out +
// g_gte. lane = point, 255 blocks x 256. Smem 43.6 KB.
// smem floats: WS [r<48][k][o:32] @0 (6144); W1 [i][j:64] @6144 (2048);
// W2 [j][o:32] @8192 (2048); GW [i][v:16] @10240 (512); biases @10752.
// -------------------------------------------------------------------------
#define W1_BIAS 10752
#define W1_SMEM_BYTES ((10752 + 144) * 4)

__global__ void __launch_bounds__(256, 2)
disco_w1(const float* __restrict__ xs,
         const float* __restrict__ W_ss, const float* __restrict__ W_vs,
         const float* __restrict__ bias_s,
         const float* __restrict__ mlp_w1, const float* __restrict__ mlp_b1,
         const float* __restrict__ mlp_w2, const float* __restrict__ mlp_b2,
         const float* __restrict__ gate_w, const float* __restrict__ gate_b,
         float* __restrict__ out) {
    extern __shared__ float sm[];
    const int tid = threadIdx.x;

    {
        const float4* g = (const float4*)W_ss;
        for (int t = tid; t < 1024; t += 256) { int o = t >> 5, i = t & 31; float4 f = g[t];
            float* b = sm + (i * 4) * 32 + o; b[0] = f.x; b[32] = f.y; b[64] = f.z; b[96] = f.w; }
        g = (const float4*)W_vs;
        for (int t = tid; t < 512; t += 256) { int o = t >> 4, i = t & 15; float4 f = g[t];
            float* b = sm + ((32 + i) * 4) * 32 + o; b[0] = f.x; b[32] = f.y; b[64] = f.z; b[96] = f.w; }
        g = (const float4*)mlp_w1;
        for (int t = tid; t < 512; t += 256) { int j = t >> 3, i4 = t & 7; float4 f = g[t];
            float* b = sm + 6144 + (i4 * 4) * 64 + j; b[0] = f.x; b[64] = f.y; b[128] = f.z; b[192] = f.w; }
        g = (const float4*)mlp_w2;
        for (int t = tid; t < 512; t += 256) { int o = t >> 4, j4 = t & 15; float4 f = g[t];
            float* b = sm + 8192 + (j4 * 4) * 32 + o; b[0] = f.x; b[32] = f.y; b[64] = f.z; b[96] = f.w; }
        g = (const float4*)gate_w;
        for (int t = tid; t < 128; t += 256) { int v = t >> 3, i4 = t & 7; float4 f = g[t];
            float* b = sm + 10240 + (i4 * 4) * 16 + v; b[0] = f.x; b[16] = f.y; b[32] = f.z; b[48] = f.w; }
        if (tid < 32) sm[W1_BIAS + tid]       = bias_s[tid];
        if (tid < 64) sm[W1_BIAS + 32 + tid]  = mlp_b1[tid];
        if (tid < 32) sm[W1_BIAS + 96 + tid]  = mlp_b2[tid];
        if (tid < 16) sm[W1_BIAS + 128 + tid] = gate_b[tid];
    }
    __syncthreads();

    const int p  = blockIdx.x * 256 + tid;
    const int pc = (p < PP) ? p : (PP - 1);

    // ---- phase S: acc (o-pairs) ----
    ull acc[16];
    #pragma unroll
    for (int qq = 0; qq < 16; qq++) acc[qq] = *(const ull*)(sm + W1_BIAS + 2 * qq);
    #pragma unroll 2
    for (int r = 0; r < 48; r++) {
        float4 z = g_Z4[r * PP + pc];
        ull zk0 = pack2(z.x, z.x), zk1 = pack2(z.y, z.y);
        ull zk2 = pack2(z.z, z.z), zk3 = pack2(z.w, z.w);
        const ulonglong2* w0 = (const ulonglong2*)(sm + r * 128);
        #pragma unroll
        for (int q2 = 0; q2 < 8; q2++) {
            ulonglong2 a = w0[q2], b = w0[8 + q2], c = w0[16 + q2], d = w0[24 + q2];
            fma2(acc[2*q2],   a.x, zk0); fma2(acc[2*q2+1], a.y, zk0);
            fma2(acc[2*q2],   b.x, zk1); fma2(acc[2*q2+1], b.y, zk1);
            fma2(acc[2*q2],   c.x, zk2); fma2(acc[2*q2+1], c.y, zk2);
            fma2(acc[2*q2],   d.x, zk3); fma2(acc[2*q2+1], d.y, zk3);
        }
    }
    float s[32];
    #pragma unroll
    for (int qq = 0; qq < 16; qq++) {
        float2 u = unpk(acc[qq]);
        s[2*qq] = gelu_exact(u.x); s[2*qq+1] = gelu_exact(u.y);
    }

    // ---- MLP (j-quarters) ----
    ull soa[16];
    #pragma unroll
    for (int qq = 0; qq < 16; qq++)
        soa[qq] = pack2(s[2*qq] + sm[W1_BIAS + 96 + 2*qq], s[2*qq+1] + sm[W1_BIAS + 97 + 2*qq]);
    #pragma unroll 1
    for (int qt = 0; qt < 4; qt++) {
        ull ha[8];
        #pragma unroll
        for (int qq = 0; qq < 8; qq++) ha[qq] = *(const ull*)(sm + W1_BIAS + 32 + qt * 16 + 2 * qq);
        #pragma unroll
        for (int i = 0; i < 32; i++) {
            ull sx = pack2(s[i], s[i]);
            const ulonglong2* w1r = (const ulonglong2*)(sm + 6144 + i * 64 + qt * 16);
            #pragma unroll
            for (int q2 = 0; q2 < 4; q2++) {
                ulonglong2 ww = w1r[q2];
                fma2(ha[2*q2], ww.x, sx); fma2(ha[2*q2+1], ww.y, sx);
            }
        }
        float hh[16];
        #pragma unroll
        for (int qq = 0; qq < 8; qq++) {
            float2 u = unpk(ha[qq]);
            hh[2*qq] = gelu_exact(u.x); hh[2*qq+1] = gelu_exact(u.y);
        }
        #pragma unroll
        for (int jj = 0; jj < 16; jj++) {
            int j = qt * 16 + jj;
            ull hx = pack2(hh[jj], hh[jj]);
            const ulonglong2* w2r = (const ulonglong2*)(sm + 8192 + j * 32);
            #pragma unroll
            for (int q2 = 0; q2 < 8; q2++) {
                ulonglong2 ww = w2r[q2];
                fma2(soa[2*q2], ww.x, hx); fma2(soa[2*q2+1], ww.y, hx);
            }
        }
    }
    float so[32];
    #pragma unroll
    for (int qq = 0; qq < 16; qq++) { float2 u = unpk(soa[qq]); so[2*qq] = u.x; so[2*qq+1] = u.y; }

    // ---- gate ----
    ull ga[8];
    #pragma unroll
    for (int qq = 0; qq < 8; qq++) ga[qq] = *(const ull*)(sm + W1_BIAS + 128 + 2 * qq);
    #pragma unroll
    for (int i = 0; i < 32; i++) {
        ull sx = pack2(so[i], so[i]);
        const ulonglong2* gr = (const ulonglong2*)(sm + 10240 + i * 16);
        #pragma unroll
        for (int q2 = 0; q2 < 4; q2++) {
            ulonglong2 ww = gr[q2];
            fma2(ga[2*q2], ww.x, sx); fma2(ga[2*q2+1], ww.y, sx);
        }
    }

    // ---- outputs: scalar out + gate ----
    if (p < PP) {
        #pragma unroll
        for (int o = 0; o < 32; o++) out[o * PP + p] = xs[o * PP + p] + so[o];
        #pragma unroll
        for (int qq = 0; qq < 8; qq++) {
            float2 u = unpk(ga[qq]);
            g_gte[(2*qq) * PP + p]     = 1.f + u.x;
            g_gte[(2*qq+1) * PP + p]   = 1.f + u.y;
        }
    }
}

// -------------------------------------------------------------------------
// Kernel B2: vector path. Light state -> high occupancy (128 thr, 5 blk/SM).
// smem floats: WV [r<48][k][o:16] @0 (3072).
// -------------------------------------------------------------------------
#define W2_SMEM_BYTES (3072 * 4)

__global__ void __launch_bounds__(128, 5)
disco_w2(const float* __restrict__ xv,
         const float* __restrict__ W_sv, const float* __restrict__ W_vv,
         float* __restrict__ out) {
    extern __shared__ float sm[];
    const int tid = threadIdx.x;

    {
        const float4* g = (const float4*)W_sv;
        for (int t = tid; t < 512; t += 128) { int o = t >> 5, i = t & 31; float4 f = g[t];
            float* b = sm + (i * 4) * 16 + o; b[0] = f.x; b[16] = f.y; b[32] = f.z; b[48] = f.w; }
        g = (const float4*)W_vv;
        for (int t = tid; t < 256; t += 128) { int o = t >> 4, i = t & 15; float4 f = g[t];
            float* b = sm + ((32 + i) * 4) * 16 + o; b[0] = f.x; b[16] = f.y; b[32] = f.z; b[48] = f.w; }
    }
    __syncthreads();

    const int p  = blockIdx.x * 128 + tid;
    const int pc = (p < PP) ? p : (PP - 1);

    // gate values
    float gte[16];
    #pragma unroll
    for (int v = 0; v < 16; v++) gte[v] = g_gte[v * PP + pc];

    // ---- phase V (o-pairs; vx = c0, vy = c1) ----
    ull vx[8], vy[8];
    #pragma unroll
    for (int qq = 0; qq < 8; qq++) { vx[qq] = 0ULL; vy[qq] = 0ULL; }
    #pragma unroll 2
    for (int r = 0; r < 32; r++) {
        float4 z0 = g_Z4[(48 + r) * PP + pc];
        float4 z1 = g_Z4[(80 + r) * PP + pc];
        ull a0 = pack2(z0.x, z0.x), a1 = pack2(z0.y, z0.y), a2 = pack2(z0.z, z0.z), a3 = pack2(z0.w, z0.w);
        ull b0 = pack2(z1.x, z1.x), b1 = pack2(z1.y, z1.y), b2 = pack2(z1.z, z1.z), b3 = pack2(z1.w, z1.w);
        const ulonglong2* wv = (const ulonglong2*)(sm + r * 64);
        #pragma unroll
        for (int q2 = 0; q2 < 4; q2++) {
            ulonglong2 wa = wv[q2], wb = wv[4 + q2], wc = wv[8 + q2], wd = wv[12 + q2];
            fma2(vx[2*q2], wa.x, a0); fma2(vx[2*q2+1], wa.y, a0);
            fma2(vy[2*q2], wa.x, b0); fma2(vy[2*q2+1], wa.y, b0);
            fma2(vx[2*q2], wb.x, a1); fma2(vx[2*q2+1], wb.y, a1);
            fma2(vy[2*q2], wb.x, b1); fma2(vy[2*q2+1], wb.y, b1);
            fma2(vx[2*q2], wc.x, a2); fma2(vx[2*q2+1], wc.y, a2);
            fma2(vy[2*q2], wc.x, b2); fma2(vy[2*q2+1], wc.y, b2);
            fma2(vx[2*q2], wd.x, a3); fma2(vx[2*q2+1], wd.y, a3);
            fma2(vy[2*q2], wd.x, b3); fma2(vy[2*q2+1], wd.y, b3);
        }
    }
    #pragma unroll 2
    for (int r = 0; r < 16; r++) {
        float4 z0 = g_Z4[(112 + r) * PP + pc];
        float4 z1 = g_Z4[(128 + r) * PP + pc];
        ull a0 = pack2(z0.x, z0.x), a1 = pack2(z0.y, z0.y), a2 = pack2(z0.z, z0.z), a3 = pack2(z0.w, z0.w);
        ull b0 = pack2(z1.x, z1.x), b1 = pack2(z1.y, z1.y), b2 = pack2(z1.z, z1.z), b3 = pack2(z1.w, z1.w);
        const ulonglong2* wv = (const ulonglong2*)(sm + (32 + r) * 64);
        #pragma unroll
        for (int q2 = 0; q2 < 4; q2++) {
            ulonglong2 wa = wv[q2], wb = wv[4 + q2], wc = wv[8 + q2], wd = wv[12 + q2];
            fma2(vx[2*q2], wa.x, a0); fma2(vx[2*q2+1], wa.y, a0);
            fma2(vy[2*q2], wa.x, b0); fma2(vy[2*q2+1], wa.y, b0);
            fma2(vx[2*q2], wb.x, a1); fma2(vx[2*q2+1], wb.y, a1);
            fma2(vy[2*q2], wb.x, b1); fma2(vy[2*q2+1], wb.y, b1);
            fma2(vx[2*q2], wc.x, a2); fma2(vx[2*q2+1], wc.y, a2);
            fma2(vy[2*q2], wc.x, b2); fma2(vy[2*q2+1], wc.y, b2);
            fma2(vx[2*q2], wd.x, a3); fma2(vx[2*q2+1], wd.y, a3);
            fma2(vy[2*q2], wd.x, b3); fma2(vy[2*q2+1], wd.y, b3);
        }
    }
    if (p < PP) {
        const float2* xv2g = (const float2*)xv;
        float2* outv = (float2*)(out + 32 * PP);
        #pragma unroll
        for (int qq = 0; qq < 8; qq++) {
            float2 ux = unpk(vx[qq]), uy = unpk(vy[qq]);
            int o0 = 2 * qq, o1 = 2 * qq + 1;
            float2 b0 = xv2g[o0 * PP + p], b1 = xv2g[o1 * PP + p];
            outv[o0 * PP + p] = make_float2(b0.x + ux.x * gte[o0], b0.y + uy.x * gte[o0]);
            outv[o1 * PP + p] = make_float2(b1.x + ux.y * gte[o1], b1.y + uy.y * gte[o1]);
        }
    }
}

extern "C" void kernel_launch(void* const* d_in, const int* in_sizes, int n_in,
                              void* d_out, int out_size) {
    const bool dictOrder = (in_sizes[2] == PP * 16);
    const float* xs = (const float*)d_in[0];
    const float* xv = (const float*)d_in[1];
    const int base = dictOrder ? 3 : 2;
    const float* pss  = (const float*)d_in[base + 0];
    const float* psv  = (const float*)d_in[base + 1];
    const float* pvs  = (const float*)d_in[base + 2];
    const float* pvv  = (const float*)d_in[base + 3];
    const float* wss  = (const float*)d_in[base + 4];
    const float* wvs  = (const float*)d_in[base + 5];
    const float* wsv  = (const float*)d_in[base + 6];
    const float* wvv  = (const float*)d_in[base + 7];
    const float* bs   = (const float*)d_in[base + 8];
    const float* w1   = (const float*)d_in[base + 9];
    const float* b1   = (const float*)d_in[base + 10];
    const float* w2   = (const float*)d_in[base + 11];
    const float* b2   = (const float*)d_in[base + 12];
    const float* gw   = (const float*)d_in[base + 13];
    const float* gb   = (const float*)d_in[base + 14];
    const int*   idx  = (const int*)(dictOrder ? d_in[2] : d_in[17]);

    cudaFuncSetAttribute(disco_z,  cudaFuncAttributeMaxDynamicSharedMemorySize, A_SMEM_BYTES);
    cudaFuncSetAttribute(disco_w1, cudaFuncAttributeMaxDynamicSharedMemorySize, W1_SMEM_BYTES);
    cudaFuncSetAttribute(disco_w2, cudaFuncAttributeMaxDynamicSharedMemorySize, W2_SMEM_BYTES);

    float* out = (float*)d_out;
    dim3 tb(32, 8);
    // position-4 launch gets profiled -> disco_w2 (the occupancy experiment)
    transpose_x<<<dim3((PP + 31) / 32, 2), tb>>>(xs, xv);
    disco_z<<<2715, 256, A_SMEM_BYTES>>>(idx, pss, psv, pvs, pvv);
    disco_w1<<<255, 256, W1_SMEM_BYTES>>>(xs, wss, wvs, bs, w1, b1, w2, b2, gw, gb, out);
    disco_w2<<<510, 128, W2_SMEM_BYTES>>>(xv, wsv, wvv, out);
}

// round 14
// speedup vs baseline: 1.2609x; 1.0652x over previous
#include <cuda_runtime.h>
#include <cuda_fp16.h>
#include <math.h>

#define PP 65160              // H*W
#define FULLM 0xffffffffu

typedef unsigned long long ull;
typedef unsigned int uint32;

// scratch
__device__ float  g_xsT[PP * 32];
__device__ float2 g_xvT2[PP * 16];
__device__ uint2  g_Zh[144 * PP];   // z features fp16x4, [fq][p] (k-packed) ~75MB
__device__ float  g_gte[16 * PP];   // gate (1+g), [v][p]

__device__ __forceinline__ float gelu_exact(float x) { return x * normcdff(x); }

__device__ __forceinline__ ull pack2(float x, float y) {
    ull r; asm("mov.b64 %0,{%1,%2};" : "=l"(r) : "f"(x), "f"(y)); return r;
}
__device__ __forceinline__ void fma2(ull& d, ull a, ull b) {
    asm("fma.rn.f32x2 %0,%1,%2,%0;" : "+l"(d) : "l"(a), "l"(b));
}
__device__ __forceinline__ float2 unpk(ull v) {
    float2 r; asm("mov.b64 {%0,%1},%2;" : "=f"(r.x), "=f"(r.y) : "l"(v)); return r;
}
// half4 (uint2) -> 4 floats
__device__ __forceinline__ void h4_to_f4(uint2 zh, float2& f0, float2& f1) {
    __half2 a = *(__half2*)&zh.x;
    __half2 b = *(__half2*)&zh.y;
    f0 = __half22float2(a);
    f1 = __half22float2(b);
}

// -------------------------------------------------------------------------
// Transpose x_scalar (32,P)->(P,32) and x_vector (16,P,2)->(P,16) float2
// -------------------------------------------------------------------------
__global__ void transpose_x(const float* __restrict__ xs,
                            const float* __restrict__ xv) {
    const int p0 = blockIdx.x * 32;
    const int tx = threadIdx.x;   // 32
    const int ty = threadIdx.y;   // 8
    if (blockIdx.y == 0) {
        __shared__ float tile[32][33];
        #pragma unroll
        for (int r = ty; r < 32; r += 8) {
            int pp = p0 + tx;
            tile[r][tx] = (pp < PP) ? xs[r * PP + pp] : 0.f;
        }
        __syncthreads();
        #pragma unroll
        for (int r = ty; r < 32; r += 8) {
            int pp = p0 + r;
            if (pp < PP) g_xsT[pp * 32 + tx] = tile[tx][r];
        }
    } else {
        __shared__ float2 t2[16][33];
        const float2* xv2 = (const float2*)xv;
        #pragma unroll
        for (int r = ty; r < 16; r += 8) {
            int pp = p0 + tx;
            t2[r][tx] = (pp < PP) ? xv2[r * PP + pp] : make_float2(0.f, 0.f);
        }
        __syncthreads();
        const int tid = ty * 32 + tx;
        #pragma unroll
        for (int q = tid; q < 512; q += 256) {
            int i = q >> 4, v = q & 15;
            int pp = p0 + i;
            if (pp < PP) g_xvT2[pp * 16 + v] = t2[v][i];
        }
    }
}

// -------------------------------------------------------------------------
// Kernel A: z producer (R10 body). Raw-psi staging, conflict-free tile
// ([pl][fq] stride 145 f4), chunked gathers; fp16 Z stores.
// fq map: 0..31 zss(i), 32..47 zvs(i), 48..79 zsv(c0,i), 80..111 zsv(c1,i),
//         112..127 zvv(c0,i), 128..143 zvv(c1,i)
// -------------------------------------------------------------------------
#define A_ZONE_OFF 13920                       // floats (tile = 3480 f4)
#define A_SMEM_FLOATS (13920 + 8 * 576)        // 18528
#define A_SMEM_BYTES (A_SMEM_FLOATS * 4)       // 74112

__global__ void __launch_bounds__(256, 2)
disco_z(const int* __restrict__ idx,
        const float* __restrict__ psi_ss, const float* __restrict__ psi_sv,
        const float* __restrict__ psi_vs, const float* __restrict__ psi_vv) {
    extern __shared__ float sm[];
    float4* T4 = (float4*)sm;
    const int tid  = threadIdx.x;
    const int warp = tid >> 5;
    const int lane = tid & 31;
    const int h    = lane >> 4;       // c / k-pair selector
    const int ch   = lane & 15;       // vector channel
    float* zone = sm + A_ZONE_OFF + warp * 576;

    const float4* gss = (const float4*)psi_ss;
    const float4* gsv = (const float4*)psi_sv;
    const float4* gvs = (const float4*)psi_vs;
    const float4* gvv = (const float4*)psi_vv;

    const int pbase = blockIdx.x * 24 + warp * 3;

    #pragma unroll 1
    for (int q = 0; q < 3; q++) {
        const int p  = pbase + q;
        const int pl = warp * 3 + q;

        int jreg = (lane < 16) ? idx[p * 16 + lane] : 0;

        // ---- load psi raw (registers) ----
        float4 fss;
        if (lane < 16) fss = gss[((lane >> 2) * PP + p) * 4 + (lane & 3)];
        float4 fsv = gsv[((lane >> 3) * PP + p) * 8 + (lane & 7)];
        float4 fvs = gvs[((lane >> 3) * PP + p) * 8 + (lane & 7)];
        float4 fv0 = gvv[(h * PP + p) * 16 + ch];
        float4 fv1 = gvv[((h + 2) * PP + p) * 16 + ch];

        // ---- stage psi (raw; only psi_vv split by c) ----
        if (lane < 16) ((float4*)zone)[lane] = fss;
        ((float4*)(zone + 64))[lane]  = fsv;
        ((float4*)(zone + 192))[lane] = fvs;
        {
            ull* pc0 = (ull*)(zone + 320);
            ull* pc1 = (ull*)(zone + 448);
            pc0[h * 16 + ch]       = pack2(fv0.x, fv0.y);   // c0, d-pair
            pc1[h * 16 + ch]       = pack2(fv0.z, fv0.w);   // c1, d-pair
            pc0[(h + 2) * 16 + ch] = pack2(fv1.x, fv1.y);
            pc1[(h + 2) * 16 + ch] = pack2(fv1.z, fv1.w);
        }
        __syncwarp();

        const ull* PssU = (const ull*)zone;                 // [k*8 + npair]
        const ull* PsvU = (const ull*)(zone + 64);          // [k*16 + n] = (c0,c1)
        const ull* PvsU = (const ull*)(zone + 192);         // [k*16 + n] = (c0,c1)
        const ull* PvvU = (const ull*)(zone + 320) + h * 64;// [k*16 + n] = (d0,d1), c=h

        ull zss[4] = {0,0,0,0};
        ull zsv[4] = {0,0,0,0};
        ull zvs0 = 0, zvs1 = 0;
        ull zvv[4] = {0,0,0,0};

        // ---- gather + accumulate in 2 chunks of 8 neighbors ----
        #pragma unroll
        for (int cH = 0; cH < 2; cH++) {
            float  xsg[8];
            float2 xvg[8];
            #pragma unroll
            for (int n8 = 0; n8 < 8; n8++) {
                int jn = __shfl_sync(FULLM, jreg, cH * 8 + n8);
                xsg[n8] = g_xsT[jn * 32 + lane];
                xvg[n8] = g_xvT2[jn * 16 + ch];
            }
            #pragma unroll
            for (int m = 0; m < 4; m++) {
                ull xp = pack2(xsg[2 * m], xsg[2 * m + 1]);
                int pr = cH * 4 + m;
                fma2(zss[0], PssU[pr],      xp);
                fma2(zss[1], PssU[8 + pr],  xp);
                fma2(zss[2], PssU[16 + pr], xp);
                fma2(zss[3], PssU[24 + pr], xp);
            }
            #pragma unroll
            for (int n8 = 0; n8 < 8; n8++) {
                int n = cH * 8 + n8;
                ull xs2 = pack2(xsg[n8], xsg[n8]);
                fma2(zsv[0], PsvU[n],      xs2);
                fma2(zsv[1], PsvU[16 + n], xs2);
                fma2(zsv[2], PsvU[32 + n], xs2);
                fma2(zsv[3], PsvU[48 + n], xs2);
                ull xvp = pack2(xvg[n8].x, xvg[n8].y);
                fma2(zvs0, PvsU[(2 * h) * 16 + n],     xvp);
                fma2(zvs1, PvsU[(2 * h + 1) * 16 + n], xvp);
                fma2(zvv[0], PvvU[n],      xvp);
                fma2(zvv[1], PvvU[16 + n], xvp);
                fma2(zvv[2], PvvU[32 + n], xvp);
                fma2(zvv[3], PvvU[48 + n], xvp);
            }
        }

        // ---- reduce + conflict-free tile stores ----
        float4* Trow = T4 + pl * 145;
        {
            float2 a0 = unpk(zss[0]), a1 = unpk(zss[1]);
            float2 a2 = unpk(zss[2]), a3 = unpk(zss[3]);
            Trow[lane] = make_float4(a0.x + a0.y, a1.x + a1.y, a2.x + a2.y, a3.x + a3.y);
        }
        {
            float2 a0 = unpk(zsv[0]), a1 = unpk(zsv[1]);
            float2 a2 = unpk(zsv[2]), a3 = unpk(zsv[3]);
            Trow[48 + lane] = make_float4(a0.x, a1.x, a2.x, a3.x);   // c0
            Trow[80 + lane] = make_float4(a0.y, a1.y, a2.y, a3.y);   // c1
        }
        {
            float2 a0 = unpk(zvs0), a1 = unpk(zvs1);
            ((ull*)&Trow[32 + ch])[h] = pack2(a0.x + a0.y, a1.x + a1.y);
        }
        {
            float2 a0 = unpk(zvv[0]), a1 = unpk(zvv[1]);
            float2 a2 = unpk(zvv[2]), a3 = unpk(zvv[3]);
            Trow[112 + lane] = make_float4(a0.x + a0.y, a1.x + a1.y, a2.x + a2.y, a3.x + a3.y);
        }
        __syncwarp();
    }

    // ---- tile -> global as fp16x4 (coalesced, conflict-free smem reads) ----
    __syncthreads();
    const int p0 = blockIdx.x * 24;
    #pragma unroll 1
    for (int t = tid; t < 144 * 24; t += 256) {
        int fq = t / 24, pl = t % 24;
        float4 z = T4[pl * 145 + fq];
        __half2 a = __floats2half2_rn(z.x, z.y);
        __half2 b = __floats2half2_rn(z.z, z.w);
        g_Zh[fq * PP + p0 + pl] = make_uint2(*(uint32*)&a, *(uint32*)&b);
    }
}

// -------------------------------------------------------------------------
// Kernel B1: scalar path (S-contraction, MLP, gate). Writes scalar out +
// g_gte. lane = point, 255 blocks x 256.
// -------------------------------------------------------------------------
#define W1_BIAS 10752
#define W1_SMEM_BYTES ((10752 + 144) * 4)

__global__ void __launch_bounds__(256, 2)
disco_w1(const float* __restrict__ xs,
         const float* __restrict__ W_ss, const float* __restrict__ W_vs,
         const float* __restrict__ bias_s,
         const float* __restrict__ mlp_w1, const float* __restrict__ mlp_b1,
         const float* __restrict__ mlp_w2, const float* __restrict__ mlp_b2,
         const float* __restrict__ gate_w, const float* __restrict__ gate_b,
         float* __restrict__ out) {
    extern __shared__ float sm[];
    const int tid = threadIdx.x;

    {
        const float4* g = (const float4*)W_ss;
        for (int t = tid; t < 1024; t += 256) { int o = t >> 5, i = t & 31; float4 f = g[t];
            float* b = sm + (i * 4) * 32 + o; b[0] = f.x; b[32] = f.y; b[64] = f.z; b[96] = f.w; }
        g = (const float4*)W_vs;
        for (int t = tid; t < 512; t += 256) { int o = t >> 4, i = t & 15; float4 f = g[t];
            float* b = sm + ((32 + i) * 4) * 32 + o; b[0] = f.x; b[32] = f.y; b[64] = f.z; b[96] = f.w; }
        g = (const float4*)mlp_w1;
        for (int t = tid; t < 512; t += 256) { int j = t >> 3, i4 = t & 7; float4 f = g[t];
            float* b = sm + 6144 + (i4 * 4) * 64 + j; b[0] = f.x; b[64] = f.y; b[128] = f.z; b[192] = f.w; }
        g = (const float4*)mlp_w2;
        for (int t = tid; t < 512; t += 256) { int o = t >> 4, j4 = t & 15; float4 f = g[t];
            float* b = sm + 8192 + (j4 * 4) * 32 + o; b[0] = f.x; b[32] = f.y; b[64] = f.z; b[96] = f.w; }
        g = (const float4*)gate_w;
        for (int t = tid; t < 128; t += 256) { int v = t >> 3, i4 = t & 7; float4 f = g[t];
            float* b = sm + 10240 + (i4 * 4) * 16 + v; b[0] = f.x; b[16] = f.y; b[32] = f.z; b[48] = f.w; }
        if (tid < 32) sm[W1_BIAS + tid]       = bias_s[tid];
        if (tid < 64) sm[W1_BIAS + 32 + tid]  = mlp_b1[tid];
        if (tid < 32) sm[W1_BIAS + 96 + tid]  = mlp_b2[tid];
        if (tid < 16) sm[W1_BIAS + 128 + tid] = gate_b[tid];
    }
    __syncthreads();

    const int p  = blockIdx.x * 256 + tid;
    const int pc = (p < PP) ? p : (PP - 1);

    // ---- phase S: acc (o-pairs) ----
    ull acc[16];
    #pragma unroll
    for (int qq = 0; qq < 16; qq++) acc[qq] = *(const ull*)(sm + W1_BIAS + 2 * qq);
    #pragma unroll 2
    for (int r = 0; r < 48; r++) {
        float2 f0, f1;
        h4_to_f4(g_Zh[r * PP + pc], f0, f1);
        ull zk0 = pack2(f0.x, f0.x), zk1 = pack2(f0.y, f0.y);
        ull zk2 = pack2(f1.x, f1.x), zk3 = pack2(f1.y, f1.y);
        const ulonglong2* w0 = (const ulonglong2*)(sm + r * 128);
        #pragma unroll
        for (int q2 = 0; q2 < 8; q2++) {
            ulonglong2 a = w0[q2], b = w0[8 + q2], c = w0[16 + q2], d = w0[24 + q2];
            fma2(acc[2*q2],   a.x, zk0); fma2(acc[2*q2+1], a.y, zk0);
            fma2(acc[2*q2],   b.x, zk1); fma2(acc[2*q2+1], b.y, zk1);
            fma2(acc[2*q2],   c.x, zk2); fma2(acc[2*q2+1], c.y, zk2);
            fma2(acc[2*q2],   d.x, zk3); fma2(acc[2*q2+1], d.y, zk3);
        }
    }
    float s[32];
    #pragma unroll
    for (int qq = 0; qq < 16; qq++) {
        float2 u = unpk(acc[qq]);
        s[2*qq] = gelu_exact(u.x); s[2*qq+1] = gelu_exact(u.y);
    }

    // ---- MLP (j-quarters) ----
    ull soa[16];
    #pragma unroll
    for (int qq = 0; qq < 16; qq++)
        soa[qq] = pack2(s[2*qq] + sm[W1_BIAS + 96 + 2*qq], s[2*qq+1] + sm[W1_BIAS + 97 + 2*qq]);
    #pragma unroll 1
    for (int qt = 0; qt < 4; qt++) {
        ull ha[8];
        #pragma unroll
        for (int qq = 0; qq < 8; qq++) ha[qq] = *(const ull*)(sm + W1_BIAS + 32 + qt * 16 + 2 * qq);
        #pragma unroll
        for (int i = 0; i < 32; i++) {
            ull sx = pack2(s[i], s[i]);
            const ulonglong2* w1r = (const ulonglong2*)(sm + 6144 + i * 64 + qt * 16);
            #pragma unroll
            for (int q2 = 0; q2 < 4; q2++) {
                ulonglong2 ww = w1r[q2];
                fma2(ha[2*q2], ww.x, sx); fma2(ha[2*q2+1], ww.y, sx);
            }
        }
        float hh[16];
        #pragma unroll
        for (int qq = 0; qq < 8; qq++) {
            float2 u = unpk(ha[qq]);
            hh[2*qq] = gelu_exact(u.x); hh[2*qq+1] = gelu_exact(u.y);
        }
        #pragma unroll
        for (int jj = 0; jj < 16; jj++) {
            int j = qt * 16 + jj;
            ull hx = pack2(hh[jj], hh[jj]);
            const ulonglong2* w2r = (const ulonglong2*)(sm + 8192 + j * 32);
            #pragma unroll
            for (int q2 = 0; q2 < 8; q2++) {
                ulonglong2 ww = w2r[q2];
                fma2(soa[2*q2], ww.x, hx); fma2(soa[2*q2+1], ww.y, hx);
            }
        }
    }
    float so[32];
    #pragma unroll
    for (int qq = 0; qq < 16; qq++) { float2 u = unpk(soa[qq]); so[2*qq] = u.x; so[2*qq+1] = u.y; }

    // ---- gate ----
    ull ga[8];
    #pragma unroll
    for (int qq = 0; qq < 8; qq++) ga[qq] = *(const ull*)(sm + W1_BIAS + 128 + 2 * qq);
    #pragma unroll
    for (int i = 0; i < 32; i++) {
        ull sx = pack2(so[i], so[i]);
        const ulonglong2* gr = (const ulonglong2*)(sm + 10240 + i * 16);
        #pragma unroll
        for (int q2 = 0; q2 < 4; q2++) {
            ulonglong2 ww = gr[q2];
            fma2(ga[2*q2], ww.x, sx); fma2(ga[2*q2+1], ww.y, sx);
        }
    }

    // ---- outputs: scalar out + gate ----
    if (p < PP) {
        #pragma unroll
        for (int o = 0; o < 32; o++) out[o * PP + p] = xs[o * PP + p] + so[o];
        #pragma unroll
        for (int qq = 0; qq < 8; qq++) {
            float2 u = unpk(ga[qq]);
            g_gte[(2*qq) * PP + p]     = 1.f + u.x;
            g_gte[(2*qq+1) * PP + p]   = 1.f + u.y;
        }
    }
}

// -------------------------------------------------------------------------
// Kernel B2: vector path. Light state, high grid.
// -------------------------------------------------------------------------
#define W2_SMEM_BYTES (3072 * 4)

__global__ void __launch_bounds__(128, 5)
disco_w2(const float* __restrict__ xv,
         const float* __restrict__ W_sv, const float* __restrict__ W_vv,
         float* __restrict__ out) {
    extern __shared__ float sm[];
    const int tid = threadIdx.x;

    {
        const float4* g = (const float4*)W_sv;
        for (int t = tid; t < 512; t += 128) { int o = t >> 5, i = t & 31; float4 f = g[t];
            float* b = sm + (i * 4) * 16 + o; b[0] = f.x; b[16] = f.y; b[32] = f.z; b[48] = f.w; }
        g = (const float4*)W_vv;
        for (int t = tid; t < 256; t += 128) { int o = t >> 4, i = t & 15; float4 f = g[t];
            float* b = sm + ((32 + i) * 4) * 16 + o; b[0] = f.x; b[16] = f.y; b[32] = f.z; b[48] = f.w; }
    }
    __syncthreads();

    const int p  = blockIdx.x * 128 + tid;
    const int pc = (p < PP) ? p : (PP - 1);

    // gate values
    float gte[16];
    #pragma unroll
    for (int v = 0; v < 16; v++) gte[v] = g_gte[v * PP + pc];

    // ---- phase V (o-pairs; vx = c0, vy = c1) ----
    ull vx[8], vy[8];
    #pragma unroll
    for (int qq = 0; qq < 8; qq++) { vx[qq] = 0ULL; vy[qq] = 0ULL; }
    #pragma unroll 2
    for (int r = 0; r < 32; r++) {
        float2 e0, e1, g0, g1;
        h4_to_f4(g_Zh[(48 + r) * PP + pc], e0, e1);
        h4_to_f4(g_Zh[(80 + r) * PP + pc], g0, g1);
        ull a0 = pack2(e0.x, e0.x), a1 = pack2(e0.y, e0.y), a2 = pack2(e1.x, e1.x), a3 = pack2(e1.y, e1.y);
        ull b0 = pack2(g0.x, g0.x), b1 = pack2(g0.y, g0.y), b2 = pack2(g1.x, g1.x), b3 = pack2(g1.y, g1.y);
        const ulonglong2* wv = (const ulonglong2*)(sm + r * 64);
        #pragma unroll
        for (int q2 = 0; q2 < 4; q2++) {
            ulonglong2 wa = wv[q2], wb = wv[4 + q2], wc = wv[8 + q2], wd = wv[12 + q2];
            fma2(vx[2*q2], wa.x, a0); fma2(vx[2*q2+1], wa.y, a0);
            fma2(vy[2*q2], wa.x, b0); fma2(vy[2*q2+1], wa.y, b0);
            fma2(vx[2*q2], wb.x, a1); fma2(vx[2*q2+1], wb.y, a1);
            fma2(vy[2*q2], wb.x, b1); fma2(vy[2*q2+1], wb.y, b1);
            fma2(vx[2*q2], wc.x, a2); fma2(vx[2*q2+1], wc.y, a2);
            fma2(vy[2*q2], wc.x, b2); fma2(vy[2*q2+1], wc.y, b2);
            fma2(vx[2*q2], wd.x, a3); fma2(vx[2*q2+1], wd.y, a3);
            fma2(vy[2*q2], wd.x, b3); fma2(vy[2*q2+1], wd.y, b3);
        }
    }
    #pragma unroll 2
    for (int r = 0; r < 16; r++) {
        float2 e0, e1, g0, g1;
        h4_to_f4(g_Zh[(112 + r) * PP + pc], e0, e1);
        h4_to_f4(g_Zh[(128 + r) * PP + pc], g0, g1);
        ull a0 = pack2(e0.x, e0.x), a1 = pack2(e0.y, e0.y), a2 = pack2(e1.x, e1.x), a3 = pack2(e1.y, e1.y);
        ull b0 = pack2(g0.x, g0.x), b1 = pack2(g0.y, g0.y), b2 = pack2(g1.x, g1.x), b3 = pack2(g1.y, g1.y);
        const ulonglong2* wv = (const ulonglong2*)(sm + (32 + r) * 64);
        #pragma unroll
        for (int q2 = 0; q2 < 4; q2++) {
            ulonglong2 wa = wv[q2], wb = wv[4 + q2], wc = wv[8 + q2], wd = wv[12 + q2];
            fma2(vx[2*q2], wa.x, a0); fma2(vx[2*q2+1], wa.y, a0);
            fma2(vy[2*q2], wa.x, b0); fma2(vy[2*q2+1], wa.y, b0);
            fma2(vx[2*q2], wb.x, a1); fma2(vx[2*q2+1], wb.y, a1);
            fma2(vy[2*q2], wb.x, b1); fma2(vy[2*q2+1], wb.y, b1);
            fma2(vx[2*q2], wc.x, a2); fma2(vx[2*q2+1], wc.y, a2);
            fma2(vy[2*q2], wc.x, b2); fma2(vy[2*q2+1], wc.y, b2);
            fma2(vx[2*q2], wd.x, a3); fma2(vx[2*q2+1], wd.y, a3);
            fma2(vy[2*q2], wd.x, b3); fma2(vy[2*q2+1], wd.y, b3);
        }
    }
    if (p < PP) {
        const float2* xv2g = (const float2*)xv;
        float2* outv = (float2*)(out + 32 * PP);
        #pragma unroll
        for (int qq = 0; qq < 8; qq++) {
            float2 ux = unpk(vx[qq]), uy = unpk(vy[qq]);
            int o0 = 2 * qq, o1 = 2 * qq + 1;
            float2 b0 = xv2g[o0 * PP + p], b1 = xv2g[o1 * PP + p];
            outv[o0 * PP + p] = make_float2(b0.x + ux.x * gte[o0], b0.y + uy.x * gte[o0]);
            outv[o1 * PP + p] = make_float2(b1.x + ux.y * gte[o1], b1.y + uy.y * gte[o1]);
        }
    }
}

extern "C" void kernel_launch(void* const* d_in, const int* in_sizes, int n_in,
                              void* d_out, int out_size) {
    const bool dictOrder = (in_sizes[2] == PP * 16);
    const float* xs = (const float*)d_in[0];
    const float* xv = (const float*)d_in[1];
    const int base = dictOrder ? 3 : 2;
    const float* pss  = (const float*)d_in[base + 0];
    const float* psv  = (const float*)d_in[base + 1];
    const float* pvs  = (const float*)d_in[base + 2];
    const float* pvv  = (const float*)d_in[base + 3];
    const float* wss  = (const float*)d_in[base + 4];
    const float* wvs  = (const float*)d_in[base + 5];
    const float* wsv  = (const float*)d_in[base + 6];
    const float* wvv  = (const float*)d_in[base + 7];
    const float* bs   = (const float*)d_in[base + 8];
    const float* w1   = (const float*)d_in[base + 9];
    const float* b1   = (const float*)d_in[base + 10];
    const float* w2   = (const float*)d_in[base + 11];
    const float* b2   = (const float*)d_in[base + 12];
    const float* gw   = (const float*)d_in[base + 13];
    const float* gb   = (const float*)d_in[base + 14];
    const int*   idx  = (const int*)(dictOrder ? d_in[2] : d_in[17]);

    cudaFuncSetAttribute(disco_z,  cudaFuncAttributeMaxDynamicSharedMemorySize, A_SMEM_BYTES);
    cudaFuncSetAttribute(disco_w1, cudaFuncAttributeMaxDynamicSharedMemorySize, W1_SMEM_BYTES);
    cudaFuncSetAttribute(disco_w2, cudaFuncAttributeMaxDynamicSharedMemorySize, W2_SMEM_BYTES);

    float* out = (float*)d_out;
    dim3 tb(32, 8);
    // position-4 launch gets profiled -> disco_w2 (direct test of L2-resident Z)
    transpose_x<<<dim3((PP + 31) / 32, 2), tb>>>(xs, xv);
    disco_z<<<2715, 256, A_SMEM_BYTES>>>(idx, pss, psv, pvs, pvv);
    disco_w1<<<255, 256, W1_SMEM_BYTES>>>(xs, wss, wvs, bs, w1, b1, w2, b2, gw, gb, out);
    disco_w2<<<510, 128, W2_SMEM_BYTES>>>(xv, wsv, wvv, out);
}

// round 15
// speedup vs baseline: 1.3380x; 1.0611x over previous
#include <cuda_runtime.h>
#include <cuda_fp16.h>
#include <math.h>

#define PP 65160              // H*W
#define FULLM 0xffffffffu

typedef unsigned long long ull;
typedef unsigned int uint32;

// scratch
__device__ float  g_xsT[PP * 32];
__device__ float2 g_xvT2[PP * 16];
__device__ uint2  g_Zh[144 * PP];   // z features fp16x4, [fq][p] (k-packed) ~75MB
__device__ float  g_gte[16 * PP];   // gate (1+g), [v][p]

__device__ __forceinline__ float gelu_exact(float x) { return x * normcdff(x); }

__device__ __forceinline__ ull pack2(float x, float y) {
    ull r; asm("mov.b64 %0,{%1,%2};" : "=l"(r) : "f"(x), "f"(y)); return r;
}
__device__ __forceinline__ void fma2(ull& d, ull a, ull b) {
    asm("fma.rn.f32x2 %0,%1,%2,%0;" : "+l"(d) : "l"(a), "l"(b));
}
__device__ __forceinline__ float2 unpk(ull v) {
    float2 r; asm("mov.b64 {%0,%1},%2;" : "=f"(r.x), "=f"(r.y) : "l"(v)); return r;
}
__device__ __forceinline__ void h4_to_f4(uint2 zh, float2& f0, float2& f1) {
    __half2 a = *(__half2*)&zh.x;
    __half2 b = *(__half2*)&zh.y;
    f0 = __half22float2(a);
    f1 = __half22float2(b);
}

// -------------------------------------------------------------------------
// Transpose x_scalar (32,P)->(P,32) and x_vector (16,P,2)->(P,16) float2
// -------------------------------------------------------------------------
__global__ void transpose_x(const float* __restrict__ xs,
                            const float* __restrict__ xv) {
    const int p0 = blockIdx.x * 32;
    const int tx = threadIdx.x;   // 32
    const int ty = threadIdx.y;   // 8
    if (blockIdx.y == 0) {
        __shared__ float tile[32][33];
        #pragma unroll
        for (int r = ty; r < 32; r += 8) {
            int pp = p0 + tx;
            tile[r][tx] = (pp < PP) ? xs[r * PP + pp] : 0.f;
        }
        __syncthreads();
        #pragma unroll
        for (int r = ty; r < 32; r += 8) {
            int pp = p0 + r;
            if (pp < PP) g_xsT[pp * 32 + tx] = tile[tx][r];
        }
    } else {
        __shared__ float2 t2[16][33];
        const float2* xv2 = (const float2*)xv;
        #pragma unroll
        for (int r = ty; r < 16; r += 8) {
            int pp = p0 + tx;
            t2[r][tx] = (pp < PP) ? xv2[r * PP + pp] : make_float2(0.f, 0.f);
        }
        __syncthreads();
        const int tid = ty * 32 + tx;
        #pragma unroll
        for (int q = tid; q < 512; q += 256) {
            int i = q >> 4, v = q & 15;
            int pp = p0 + i;
            if (pp < PP) g_xvT2[pp * 16 + v] = t2[v][i];
        }
    }
}

// profile-window steering: position-4 launch gets captured
__global__ void prof_marker() {}

// -------------------------------------------------------------------------
// Kernel A: z producer (R10 body). fp16 Z stores.
// fq map: 0..31 zss(i), 32..47 zvs(i), 48..79 zsv(c0,i), 80..111 zsv(c1,i),
//         112..127 zvv(c0,i), 128..143 zvv(c1,i)
// -------------------------------------------------------------------------
#define A_ZONE_OFF 13920                       // floats (tile = 3480 f4)
#define A_SMEM_FLOATS (13920 + 8 * 576)        // 18528
#define A_SMEM_BYTES (A_SMEM_FLOATS * 4)       // 74112

__global__ void __launch_bounds__(256, 2)
disco_z(const int* __restrict__ idx,
        const float* __restrict__ psi_ss, const float* __restrict__ psi_sv,
        const float* __restrict__ psi_vs, const float* __restrict__ psi_vv) {
    extern __shared__ float sm[];
    float4* T4 = (float4*)sm;
    const int tid  = threadIdx.x;
    const int warp = tid >> 5;
    const int lane = tid & 31;
    const int h    = lane >> 4;       // c / k-pair selector
    const int ch   = lane & 15;       // vector channel
    float* zone = sm + A_ZONE_OFF + warp * 576;

    const float4* gss = (const float4*)psi_ss;
    const float4* gsv = (const float4*)psi_sv;
    const float4* gvs = (const float4*)psi_vs;
    const float4* gvv = (const float4*)psi_vv;

    const int pbase = blockIdx.x * 24 + warp * 3;

    #pragma unroll 1
    for (int q = 0; q < 3; q++) {
        const int p  = pbase + q;
        const int pl = warp * 3 + q;

        int jreg = (lane < 16) ? idx[p * 16 + lane] : 0;

        // ---- load psi raw (registers) ----
        float4 fss;
        if (lane < 16) fss = gss[((lane >> 2) * PP + p) * 4 + (lane & 3)];
        float4 fsv = gsv[((lane >> 3) * PP + p) * 8 + (lane & 7)];
        float4 fvs = gvs[((lane >> 3) * PP + p) * 8 + (lane & 7)];
        float4 fv0 = gvv[(h * PP + p) * 16 + ch];
        float4 fv1 = gvv[((h + 2) * PP + p) * 16 + ch];

        // ---- stage psi (raw; only psi_vv split by c) ----
        if (lane < 16) ((float4*)zone)[lane] = fss;
        ((float4*)(zone + 64))[lane]  = fsv;
        ((float4*)(zone + 192))[lane] = fvs;
        {
            ull* pc0 = (ull*)(zone + 320);
            ull* pc1 = (ull*)(zone + 448);
            pc0[h * 16 + ch]       = pack2(fv0.x, fv0.y);   // c0, d-pair
            pc1[h * 16 + ch]       = pack2(fv0.z, fv0.w);   // c1, d-pair
            pc0[(h + 2) * 16 + ch] = pack2(fv1.x, fv1.y);
            pc1[(h + 2) * 16 + ch] = pack2(fv1.z, fv1.w);
        }
        __syncwarp();

        const ull* PssU = (const ull*)zone;                 // [k*8 + npair]
        const ull* PsvU = (const ull*)(zone + 64);          // [k*16 + n] = (c0,c1)
        const ull* PvsU = (const ull*)(zone + 192);         // [k*16 + n] = (c0,c1)
        const ull* PvvU = (const ull*)(zone + 320) + h * 64;// [k*16 + n] = (d0,d1), c=h

        ull zss[4] = {0,0,0,0};
        ull zsv[4] = {0,0,0,0};
        ull zvs0 = 0, zvs1 = 0;
        ull zvv[4] = {0,0,0,0};

        // ---- gather + accumulate in 2 chunks of 8 neighbors ----
        #pragma unroll
        for (int cH = 0; cH < 2; cH++) {
            float  xsg[8];
            float2 xvg[8];
            #pragma unroll
            for (int n8 = 0; n8 < 8; n8++) {
                int jn = __shfl_sync(FULLM, jreg, cH * 8 + n8);
                xsg[n8] = g_xsT[jn * 32 + lane];
                xvg[n8] = g_xvT2[jn * 16 + ch];
            }
            #pragma unroll
            for (int m = 0; m < 4; m++) {
                ull xp = pack2(xsg[2 * m], xsg[2 * m + 1]);
                int pr = cH * 4 + m;
                fma2(zss[0], PssU[pr],      xp);
                fma2(zss[1], PssU[8 + pr],  xp);
                fma2(zss[2], PssU[16 + pr], xp);
                fma2(zss[3], PssU[24 + pr], xp);
            }
            #pragma unroll
            for (int n8 = 0; n8 < 8; n8++) {
                int n = cH * 8 + n8;
                ull xs2 = pack2(xsg[n8], xsg[n8]);
                fma2(zsv[0], PsvU[n],      xs2);
                fma2(zsv[1], PsvU[16 + n], xs2);
                fma2(zsv[2], PsvU[32 + n], xs2);
                fma2(zsv[3], PsvU[48 + n], xs2);
                ull xvp = pack2(xvg[n8].x, xvg[n8].y);
                fma2(zvs0, PvsU[(2 * h) * 16 + n],     xvp);
                fma2(zvs1, PvsU[(2 * h + 1) * 16 + n], xvp);
                fma2(zvv[0], PvvU[n],      xvp);
                fma2(zvv[1], PvvU[16 + n], xvp);
                fma2(zvv[2], PvvU[32 + n], xvp);
                fma2(zvv[3], PvvU[48 + n], xvp);
            }
        }

        // ---- reduce + conflict-free tile stores ----
        float4* Trow = T4 + pl * 145;
        {
            float2 a0 = unpk(zss[0]), a1 = unpk(zss[1]);
            float2 a2 = unpk(zss[2]), a3 = unpk(zss[3]);
            Trow[lane] = make_float4(a0.x + a0.y, a1.x + a1.y, a2.x + a2.y, a3.x + a3.y);
        }
        {
            float2 a0 = unpk(zsv[0]), a1 = unpk(zsv[1]);
            float2 a2 = unpk(zsv[2]), a3 = unpk(zsv[3]);
            Trow[48 + lane] = make_float4(a0.x, a1.x, a2.x, a3.x);   // c0
            Trow[80 + lane] = make_float4(a0.y, a1.y, a2.y, a3.y);   // c1
        }
        {
            float2 a0 = unpk(zvs0), a1 = unpk(zvs1);
            ((ull*)&Trow[32 + ch])[h] = pack2(a0.x + a0.y, a1.x + a1.y);
        }
        {
            float2 a0 = unpk(zvv[0]), a1 = unpk(zvv[1]);
            float2 a2 = unpk(zvv[2]), a3 = unpk(zvv[3]);
            Trow[112 + lane] = make_float4(a0.x + a0.y, a1.x + a1.y, a2.x + a2.y, a3.x + a3.y);
        }
        __syncwarp();
    }

    // ---- tile -> global as fp16x4 ----
    __syncthreads();
    const int p0 = blockIdx.x * 24;
    #pragma unroll 1
    for (int t = tid; t < 144 * 24; t += 256) {
        int fq = t / 24, pl = t % 24;
        float4 z = T4[pl * 145 + fq];
        __half2 a = __floats2half2_rn(z.x, z.y);
        __half2 b = __floats2half2_rn(z.z, z.w);
        g_Zh[fq * PP + p0 + pl] = make_uint2(*(uint32*)&a, *(uint32*)&b);
    }
}

// -------------------------------------------------------------------------
// Kernel W12: merged consumer. Blocks [0,255): scalar path (S, MLP, gate ->
// scalar out + g_gte). Blocks [255,510): vector path (V -> RAW v to out).
// Both paths co-resident per SM -> mutual latency hiding.
// -------------------------------------------------------------------------
#define W1_BIAS 10752
#define W12_SMEM_BYTES ((10752 + 144) * 4)

__global__ void __launch_bounds__(256, 2)
disco_w12(const float* __restrict__ xs,
          const float* __restrict__ W_ss, const float* __restrict__ W_vs,
          const float* __restrict__ W_sv, const float* __restrict__ W_vv,
          const float* __restrict__ bias_s,
          const float* __restrict__ mlp_w1, const float* __restrict__ mlp_b1,
          const float* __restrict__ mlp_w2, const float* __restrict__ mlp_b2,
          const float* __restrict__ gate_w, const float* __restrict__ gate_b,
          float* __restrict__ out) {
    extern __shared__ float sm[];
    const int tid = threadIdx.x;

    if (blockIdx.x < 255) {
        // ================= scalar path =================
        {
            const float4* g = (const float4*)W_ss;
            for (int t = tid; t < 1024; t += 256) { int o = t >> 5, i = t & 31; float4 f = g[t];
                float* b = sm + (i * 4) * 32 + o; b[0] = f.x; b[32] = f.y; b[64] = f.z; b[96] = f.w; }
            g = (const float4*)W_vs;
            for (int t = tid; t < 512; t += 256) { int o = t >> 4, i = t & 15; float4 f = g[t];
                float* b = sm + ((32 + i) * 4) * 32 + o; b[0] = f.x; b[32] = f.y; b[64] = f.z; b[96] = f.w; }
            g = (const float4*)mlp_w1;
            for (int t = tid; t < 512; t += 256) { int j = t >> 3, i4 = t & 7; float4 f = g[t];
                float* b = sm + 6144 + (i4 * 4) * 64 + j; b[0] = f.x; b[64] = f.y; b[128] = f.z; b[192] = f.w; }
            g = (const float4*)mlp_w2;
            for (int t = tid; t < 512; t += 256) { int o = t >> 4, j4 = t & 15; float4 f = g[t];
                float* b = sm + 8192 + (j4 * 4) * 32 + o; b[0] = f.x; b[32] = f.y; b[64] = f.z; b[96] = f.w; }
            g = (const float4*)gate_w;
            for (int t = tid; t < 128; t += 256) { int v = t >> 3, i4 = t & 7; float4 f = g[t];
                float* b = sm + 10240 + (i4 * 4) * 16 + v; b[0] = f.x; b[16] = f.y; b[32] = f.z; b[48] = f.w; }
            if (tid < 32) sm[W1_BIAS + tid]       = bias_s[tid];
            if (tid < 64) sm[W1_BIAS + 32 + tid]  = mlp_b1[tid];
            if (tid < 32) sm[W1_BIAS + 96 + tid]  = mlp_b2[tid];
            if (tid < 16) sm[W1_BIAS + 128 + tid] = gate_b[tid];
        }
        __syncthreads();

        const int p  = blockIdx.x * 256 + tid;
        const int pc = (p < PP) ? p : (PP - 1);

        // ---- phase S ----
        ull acc[16];
        #pragma unroll
        for (int qq = 0; qq < 16; qq++) acc[qq] = *(const ull*)(sm + W1_BIAS + 2 * qq);
        #pragma unroll 4
        for (int r = 0; r < 48; r++) {
            float2 f0, f1;
            h4_to_f4(g_Zh[r * PP + pc], f0, f1);
            ull zk0 = pack2(f0.x, f0.x), zk1 = pack2(f0.y, f0.y);
            ull zk2 = pack2(f1.x, f1.x), zk3 = pack2(f1.y, f1.y);
            const ulonglong2* w0 = (const ulonglong2*)(sm + r * 128);
            #pragma unroll
            for (int q2 = 0; q2 < 8; q2++) {
                ulonglong2 a = w0[q2], b = w0[8 + q2], c = w0[16 + q2], d = w0[24 + q2];
                fma2(acc[2*q2],   a.x, zk0); fma2(acc[2*q2+1], a.y, zk0);
                fma2(acc[2*q2],   b.x, zk1); fma2(acc[2*q2+1], b.y, zk1);
                fma2(acc[2*q2],   c.x, zk2); fma2(acc[2*q2+1], c.y, zk2);
                fma2(acc[2*q2],   d.x, zk3); fma2(acc[2*q2+1], d.y, zk3);
            }
        }
        float s[32];
        #pragma unroll
        for (int qq = 0; qq < 16; qq++) {
            float2 u = unpk(acc[qq]);
            s[2*qq] = gelu_exact(u.x); s[2*qq+1] = gelu_exact(u.y);
        }

        // ---- MLP (j-quarters) ----
        ull soa[16];
        #pragma unroll
        for (int qq = 0; qq < 16; qq++)
            soa[qq] = pack2(s[2*qq] + sm[W1_BIAS + 96 + 2*qq], s[2*qq+1] + sm[W1_BIAS + 97 + 2*qq]);
        #pragma unroll 1
        for (int qt = 0; qt < 4; qt++) {
            ull ha[8];
            #pragma unroll
            for (int qq = 0; qq < 8; qq++) ha[qq] = *(const ull*)(sm + W1_BIAS + 32 + qt * 16 + 2 * qq);
            #pragma unroll
            for (int i = 0; i < 32; i++) {
                ull sx = pack2(s[i], s[i]);
                const ulonglong2* w1r = (const ulonglong2*)(sm + 6144 + i * 64 + qt * 16);
                #pragma unroll
                for (int q2 = 0; q2 < 4; q2++) {
                    ulonglong2 ww = w1r[q2];
                    fma2(ha[2*q2], ww.x, sx); fma2(ha[2*q2+1], ww.y, sx);
                }
            }
            float hh[16];
            #pragma unroll
            for (int qq = 0; qq < 8; qq++) {
                float2 u = unpk(ha[qq]);
                hh[2*qq] = gelu_exact(u.x); hh[2*qq+1] = gelu_exact(u.y);
            }
            #pragma unroll
            for (int jj = 0; jj < 16; jj++) {
                int j = qt * 16 + jj;
                ull hx = pack2(hh[jj], hh[jj]);
                const ulonglong2* w2r = (const ulonglong2*)(sm + 8192 + j * 32);
                #pragma unroll
                for (int q2 = 0; q2 < 8; q2++) {
                    ulonglong2 ww = w2r[q2];
                    fma2(soa[2*q2], ww.x, hx); fma2(soa[2*q2+1], ww.y, hx);
                }
            }
        }
        float so[32];
        #pragma unroll
        for (int qq = 0; qq < 16; qq++) { float2 u = unpk(soa[qq]); so[2*qq] = u.x; so[2*qq+1] = u.y; }

        // ---- gate ----
        ull ga[8];
        #pragma unroll
        for (int qq = 0; qq < 8; qq++) ga[qq] = *(const ull*)(sm + W1_BIAS + 128 + 2 * qq);
        #pragma unroll
        for (int i = 0; i < 32; i++) {
            ull sx = pack2(so[i], so[i]);
            const ulonglong2* gr = (const ulonglong2*)(sm + 10240 + i * 16);
            #pragma unroll
            for (int q2 = 0; q2 < 4; q2++) {
                ulonglong2 ww = gr[q2];
                fma2(ga[2*q2], ww.x, sx); fma2(ga[2*q2+1], ww.y, sx);
            }
        }

        if (p < PP) {
            #pragma unroll
            for (int o = 0; o < 32; o++) out[o * PP + p] = xs[o * PP + p] + so[o];
            #pragma unroll
            for (int qq = 0; qq < 8; qq++) {
                float2 u = unpk(ga[qq]);
                g_gte[(2*qq) * PP + p]   = 1.f + u.x;
                g_gte[(2*qq+1) * PP + p] = 1.f + u.y;
            }
        }
    } else {
        // ================= vector path (raw v, no gate) =================
        {
            const float4* g = (const float4*)W_sv;
            for (int t = tid; t < 512; t += 256) { int o = t >> 5, i = t & 31; float4 f = g[t];
                float* b = sm + (i * 4) * 16 + o; b[0] = f.x; b[16] = f.y; b[32] = f.z; b[48] = f.w; }
            g = (const float4*)W_vv;
            for (int t = tid; t < 256; t += 256) { int o = t >> 4, i = t & 15; float4 f = g[t];
                float* b = sm + ((32 + i) * 4) * 16 + o; b[0] = f.x; b[16] = f.y; b[32] = f.z; b[48] = f.w; }
        }
        __syncthreads();

        const int p  = (blockIdx.x - 255) * 256 + tid;
        const int pc = (p < PP) ? p : (PP - 1);

        ull vx[8], vy[8];
        #pragma unroll
        for (int qq = 0; qq < 8; qq++) { vx[qq] = 0ULL; vy[qq] = 0ULL; }
        #pragma unroll 4
        for (int r = 0; r < 32; r++) {
            float2 e0, e1, g0, g1;
            h4_to_f4(g_Zh[(48 + r) * PP + pc], e0, e1);
            h4_to_f4(g_Zh[(80 + r) * PP + pc], g0, g1);
            ull a0 = pack2(e0.x, e0.x), a1 = pack2(e0.y, e0.y), a2 = pack2(e1.x, e1.x), a3 = pack2(e1.y, e1.y);
            ull b0 = pack2(g0.x, g0.x), b1 = pack2(g0.y, g0.y), b2 = pack2(g1.x, g1.x), b3 = pack2(g1.y, g1.y);
            const ulonglong2* wv = (const ulonglong2*)(sm + r * 64);
            #pragma unroll
            for (int q2 = 0; q2 < 4; q2++) {
                ulonglong2 wa = wv[q2], wb = wv[4 + q2], wc = wv[8 + q2], wd = wv[12 + q2];
                fma2(vx[2*q2], wa.x, a0); fma2(vx[2*q2+1], wa.y, a0);
                fma2(vy[2*q2], wa.x, b0); fma2(vy[2*q2+1], wa.y, b0);
                fma2(vx[2*q2], wb.x, a1); fma2(vx[2*q2+1], wb.y, a1);
                fma2(vy[2*q2], wb.x, b1); fma2(vy[2*q2+1], wb.y, b1);
                fma2(vx[2*q2], wc.x, a2); fma2(vx[2*q2+1], wc.y, a2);
                fma2(vy[2*q2], wc.x, b2); fma2(vy[2*q2+1], wc.y, b2);
                fma2(vx[2*q2], wd.x, a3); fma2(vx[2*q2+1], wd.y, a3);
                fma2(vy[2*q2], wd.x, b3); fma2(vy[2*q2+1], wd.y, b3);
            }
        }
        #pragma unroll 4
        for (int r = 0; r < 16; r++) {
            float2 e0, e1, g0, g1;
            h4_to_f4(g_Zh[(112 + r) * PP + pc], e0, e1);
            h4_to_f4(g_Zh[(128 + r) * PP + pc], g0, g1);
            ull a0 = pack2(e0.x, e0.x), a1 = pack2(e0.y, e0.y), a2 = pack2(e1.x, e1.x), a3 = pack2(e1.y, e1.y);
            ull b0 = pack2(g0.x, g0.x), b1 = pack2(g0.y, g0.y), b2 = pack2(g1.x, g1.x), b3 = pack2(g1.y, g1.y);
            const ulonglong2* wv = (const ulonglong2*)(sm + (32 + r) * 64);
            #pragma unroll
            for (int q2 = 0; q2 < 4; q2++) {
                ulonglong2 wa = wv[q2], wb = wv[4 + q2], wc = wv[8 + q2], wd = wv[12 + q2];
                fma2(vx[2*q2], wa.x, a0); fma2(vx[2*q2+1], wa.y, a0);
                fma2(vy[2*q2], wa.x, b0); fma2(vy[2*q2+1], wa.y, b0);
                fma2(vx[2*q2], wb.x, a1); fma2(vx[2*q2+1], wb.y, a1);
                fma2(vy[2*q2], wb.x, b1); fma2(vy[2*q2+1], wb.y, b1);
                fma2(vx[2*q2], wc.x, a2); fma2(vx[2*q2+1], wc.y, a2);
                fma2(vy[2*q2], wc.x, b2); fma2(vy[2*q2+1], wc.y, b2);
                fma2(vx[2*q2], wd.x, a3); fma2(vx[2*q2+1], wd.y, a3);
                fma2(vy[2*q2], wd.x, b3); fma2(vy[2*q2+1], wd.y, b3);
            }
        }
        if (p < PP) {
            float2* outv = (float2*)(out + 32 * PP);
            #pragma unroll
            for (int qq = 0; qq < 8; qq++) {
                float2 ux = unpk(vx[qq]), uy = unpk(vy[qq]);
                int o0 = 2 * qq, o1 = 2 * qq + 1;
                outv[o0 * PP + p] = make_float2(ux.x, uy.x);   // raw v
                outv[o1 * PP + p] = make_float2(ux.y, uy.y);
            }
        }
    }
}

// -------------------------------------------------------------------------
// Kernel W3: combiner. out_v = xv + gte * raw_v
// -------------------------------------------------------------------------
__global__ void disco_w3(const float* __restrict__ xv, float* __restrict__ out) {
    const int p = blockIdx.x * 256 + threadIdx.x;
    const int v = blockIdx.y;
    if (p < PP) {
        float g = g_gte[v * PP + p];
        float2* outv = (float2*)(out + 32 * PP);
        const float2* xv2 = (const float2*)xv;
        float2 raw = outv[v * PP + p];
        float2 b   = xv2[v * PP + p];
        outv[v * PP + p] = make_float2(b.x + g * raw.x, b.y + g * raw.y);
    }
}

extern "C" void kernel_launch(void* const* d_in, const int* in_sizes, int n_in,
                              void* d_out, int out_size) {
    const bool dictOrder = (in_sizes[2] == PP * 16);
    const float* xs = (const float*)d_in[0];
    const float* xv = (const float*)d_in[1];
    const int base = dictOrder ? 3 : 2;
    const float* pss  = (const float*)d_in[base + 0];
    const float* psv  = (const float*)d_in[base + 1];
    const float* pvs  = (const float*)d_in[base + 2];
    const float* pvv  = (const float*)d_in[base + 3];
    const float* wss  = (const float*)d_in[base + 4];
    const float* wvs  = (const float*)d_in[base + 5];
    const float* wsv  = (const float*)d_in[base + 6];
    const float* wvv  = (const float*)d_in[base + 7];
    const float* bs   = (const float*)d_in[base + 8];
    const float* w1   = (const float*)d_in[base + 9];
    const float* b1   = (const float*)d_in[base + 10];
    const float* w2   = (const float*)d_in[base + 11];
    const float* b2   = (const float*)d_in[base + 12];
    const float* gw   = (const float*)d_in[base + 13];
    const float* gb   = (const float*)d_in[base + 14];
    const int*   idx  = (const int*)(dictOrder ? d_in[2] : d_in[17]);

    cudaFuncSetAttribute(disco_z,   cudaFuncAttributeMaxDynamicSharedMemorySize, A_SMEM_BYTES);
    cudaFuncSetAttribute(disco_w12, cudaFuncAttributeMaxDynamicSharedMemorySize, W12_SMEM_BYTES);

    float* out = (float*)d_out;
    dim3 tb(32, 8);
    // position-4 launch gets profiled -> disco_w12 (the concurrency experiment)
    prof_marker<<<1, 32>>>();
    transpose_x<<<dim3((PP + 31) / 32, 2), tb>>>(xs, xv);
    disco_z<<<2715, 256, A_SMEM_BYTES>>>(idx, pss, psv, pvs, pvv);
    disco_w12<<<510, 256, W12_SMEM_BYTES>>>(xs, wss, wvs, wsv, wvv, bs,
                                            w1, b1, w2, b2, gw, gb, out);
    disco_w3<<<dim3(255, 16), 256>>>(xv, out);
}

// round 16
// speedup vs baseline: 1.3429x; 1.0036x over previous
#include <cuda_runtime.h>
#include <cuda_fp16.h>
#include <math.h>

#define PP 65160              // H*W
#define FULLM 0xffffffffu

typedef unsigned long long ull;
typedef unsigned int uint32;

// scratch
__device__ float  g_xsT[PP * 32];
__device__ float2 g_xvT2[PP * 16];
__device__ uint2  g_Zh[144 * PP];   // z features fp16x4, [fq][p] (k-packed) ~75MB
__device__ float  g_gte[16 * PP];   // gate (1+g), [v][p]

__device__ __forceinline__ float gelu_exact(float x) { return x * normcdff(x); }

__device__ __forceinline__ ull pack2(float x, float y) {
    ull r; asm("mov.b64 %0,{%1,%2};" : "=l"(r) : "f"(x), "f"(y)); return r;
}
__device__ __forceinline__ void fma2(ull& d, ull a, ull b) {
    asm("fma.rn.f32x2 %0,%1,%2,%0;" : "+l"(d) : "l"(a), "l"(b));
}
__device__ __forceinline__ float2 unpk(ull v) {
    float2 r; asm("mov.b64 {%0,%1},%2;" : "=f"(r.x), "=f"(r.y) : "l"(v)); return r;
}
__device__ __forceinline__ void h4_to_f4(uint2 zh, float2& f0, float2& f1) {
    __half2 a = *(__half2*)&zh.x;
    __half2 b = *(__half2*)&zh.y;
    f0 = __half22float2(a);
    f1 = __half22float2(b);
}

// -------------------------------------------------------------------------
// Transpose x_scalar (32,P)->(P,32) and x_vector (16,P,2)->(P,16) float2
// -------------------------------------------------------------------------
__global__ void transpose_x(const float* __restrict__ xs,
                            const float* __restrict__ xv) {
    const int p0 = blockIdx.x * 32;
    const int tx = threadIdx.x;   // 32
    const int ty = threadIdx.y;   // 8
    if (blockIdx.y == 0) {
        __shared__ float tile[32][33];
        #pragma unroll
        for (int r = ty; r < 32; r += 8) {
            int pp = p0 + tx;
            tile[r][tx] = (pp < PP) ? xs[r * PP + pp] : 0.f;
        }
        __syncthreads();
        #pragma unroll
        for (int r = ty; r < 32; r += 8) {
            int pp = p0 + r;
            if (pp < PP) g_xsT[pp * 32 + tx] = tile[tx][r];
        }
    } else {
        __shared__ float2 t2[16][33];
        const float2* xv2 = (const float2*)xv;
        #pragma unroll
        for (int r = ty; r < 16; r += 8) {
            int pp = p0 + tx;
            t2[r][tx] = (pp < PP) ? xv2[r * PP + pp] : make_float2(0.f, 0.f);
        }
        __syncthreads();
        const int tid = ty * 32 + tx;
        #pragma unroll
        for (int q = tid; q < 512; q += 256) {
            int i = q >> 4, v = q & 15;
            int pp = p0 + i;
            if (pp < PP) g_xvT2[pp * 16 + v] = t2[v][i];
        }
    }
}

// -------------------------------------------------------------------------
// Kernel A: z producer. R10 staging UNCHANGED; z-math restructured so every
// psi load is a paired LDS.128 (96/pt instead of 192 LDS.64/pt).
// fq map: 0..31 zss(i), 32..47 zvs(i), 48..79 zsv(c0,i), 80..111 zsv(c1,i),
//         112..127 zvv(c0,i), 128..143 zvv(c1,i)
// -------------------------------------------------------------------------
#define A_ZONE_OFF 13920                       // floats (tile = 3480 f4)
#define A_SMEM_FLOATS (13920 + 8 * 576)        // 18528
#define A_SMEM_BYTES (A_SMEM_FLOATS * 4)       // 74112

__global__ void __launch_bounds__(256, 2)
disco_z(const int* __restrict__ idx,
        const float* __restrict__ psi_ss, const float* __restrict__ psi_sv,
        const float* __restrict__ psi_vs, const float* __restrict__ psi_vv) {
    extern __shared__ float sm[];
    float4* T4 = (float4*)sm;
    const int tid  = threadIdx.x;
    const int warp = tid >> 5;
    const int lane = tid & 31;
    const int h    = lane >> 4;       // c / k-pair selector
    const int ch   = lane & 15;       // vector channel
    float* zone = sm + A_ZONE_OFF + warp * 576;

    const float4* gss = (const float4*)psi_ss;
    const float4* gsv = (const float4*)psi_sv;
    const float4* gvs = (const float4*)psi_vs;
    const float4* gvv = (const float4*)psi_vv;

    const int pbase = blockIdx.x * 24 + warp * 3;

    #pragma unroll 1
    for (int q = 0; q < 3; q++) {
        const int p  = pbase + q;
        const int pl = warp * 3 + q;

        int jreg = (lane < 16) ? idx[p * 16 + lane] : 0;

        // ---- load psi raw (registers) ----
        float4 fss;
        if (lane < 16) fss = gss[((lane >> 2) * PP + p) * 4 + (lane & 3)];
        float4 fsv = gsv[((lane >> 3) * PP + p) * 8 + (lane & 7)];
        float4 fvs = gvs[((lane >> 3) * PP + p) * 8 + (lane & 7)];
        float4 fv0 = gvv[(h * PP + p) * 16 + ch];
        float4 fv1 = gvv[((h + 2) * PP + p) * 16 + ch];

        // ---- stage psi (raw; only psi_vv split by c) — UNCHANGED ----
        if (lane < 16) ((float4*)zone)[lane] = fss;
        ((float4*)(zone + 64))[lane]  = fsv;
        ((float4*)(zone + 192))[lane] = fvs;
        {
            ull* pc0 = (ull*)(zone + 320);
            ull* pc1 = (ull*)(zone + 448);
            pc0[h * 16 + ch]       = pack2(fv0.x, fv0.y);   // c0, d-pair
            pc1[h * 16 + ch]       = pack2(fv0.z, fv0.w);   // c1, d-pair
            pc0[(h + 2) * 16 + ch] = pack2(fv1.x, fv1.y);
            pc1[(h + 2) * 16 + ch] = pack2(fv1.z, fv1.w);
        }
        __syncwarp();

        // ull2 views over the same layouts
        const ulonglong2* Pss2 = (const ulonglong2*)zone;          // [k*4 + np/2]
        const ulonglong2* Psv2 = (const ulonglong2*)(zone + 64);   // [k*8 + n/2]
        const ulonglong2* Pvs2 = (const ulonglong2*)(zone + 192);  // [k*8 + n/2]
        const ulonglong2* Pvv2 = (const ulonglong2*)(zone + 320) + h * 32; // [k*8 + n/2]

        ull zss[4] = {0,0,0,0};
        ull zsv[4] = {0,0,0,0};
        ull zvs0 = 0, zvs1 = 0;
        ull zvv[4] = {0,0,0,0};

        // ---- gather + accumulate in 2 chunks of 8 neighbors ----
        #pragma unroll
        for (int cH = 0; cH < 2; cH++) {
            float  xsg[8];
            float2 xvg[8];
            #pragma unroll
            for (int n8 = 0; n8 < 8; n8++) {
                int jn = __shfl_sync(FULLM, jreg, cH * 8 + n8);
                xsg[n8] = g_xsT[jn * 32 + lane];
                xvg[n8] = g_xvT2[jn * 16 + ch];
            }

            // zss: psi n-pairs, paired loads (2 LDS.128 per k per chunk)
            {
                ull xp0 = pack2(xsg[0], xsg[1]);
                ull xp1 = pack2(xsg[2], xsg[3]);
                ull xp2 = pack2(xsg[4], xsg[5]);
                ull xp3 = pack2(xsg[6], xsg[7]);
                #pragma unroll
                for (int k = 0; k < 4; k++) {
                    ulonglong2 qa = Pss2[k * 4 + cH * 2];
                    ulonglong2 qb = Pss2[k * 4 + cH * 2 + 1];
                    fma2(zss[k], qa.x, xp0); fma2(zss[k], qa.y, xp1);
                    fma2(zss[k], qb.x, xp2); fma2(zss[k], qb.y, xp3);
                }
            }

            // zsv / zvs / zvv: n-pair outer, paired LDS.128
            #pragma unroll
            for (int j = 0; j < 4; j++) {
                ull xa0 = pack2(xsg[2*j],     xsg[2*j]);
                ull xa1 = pack2(xsg[2*j + 1], xsg[2*j + 1]);
                ull xv0 = pack2(xvg[2*j].x,     xvg[2*j].y);
                ull xv1 = pack2(xvg[2*j + 1].x, xvg[2*j + 1].y);
                #pragma unroll
                for (int k = 0; k < 4; k++) {
                    ulonglong2 qs = Psv2[k * 8 + cH * 4 + j];
                    fma2(zsv[k], qs.x, xa0); fma2(zsv[k], qs.y, xa1);
                    ulonglong2 qv = Pvv2[k * 8 + cH * 4 + j];
                    fma2(zvv[k], qv.x, xv0); fma2(zvv[k], qv.y, xv1);
                }
                ulonglong2 q0 = Pvs2[(2 * h) * 8 + cH * 4 + j];
                ulonglong2 q1 = Pvs2[(2 * h + 1) * 8 + cH * 4 + j];
                fma2(zvs0, q0.x, xv0); fma2(zvs0, q0.y, xv1);
                fma2(zvs1, q1.x, xv0); fma2(zvs1, q1.y, xv1);
            }
        }

        // ---- reduce + conflict-free tile stores (UNCHANGED) ----
        float4* Trow = T4 + pl * 145;
        {
            float2 a0 = unpk(zss[0]), a1 = unpk(zss[1]);
            float2 a2 = unpk(zss[2]), a3 = unpk(zss[3]);
            Trow[lane] = make_float4(a0.x + a0.y, a1.x + a1.y, a2.x + a2.y, a3.x + a3.y);
        }
        {
            float2 a0 = unpk(zsv[0]), a1 = unpk(zsv[1]);
            float2 a2 = unpk(zsv[2]), a3 = unpk(zsv[3]);
            Trow[48 + lane] = make_float4(a0.x, a1.x, a2.x, a3.x);   // c0
            Trow[80 + lane] = make_float4(a0.y, a1.y, a2.y, a3.y);   // c1
        }
        {
            float2 a0 = unpk(zvs0), a1 = unpk(zvs1);
            ((ull*)&Trow[32 + ch])[h] = pack2(a0.x + a0.y, a1.x + a1.y);
        }
        {
            float2 a0 = unpk(zvv[0]), a1 = unpk(zvv[1]);
            float2 a2 = unpk(zvv[2]), a3 = unpk(zvv[3]);
            Trow[112 + lane] = make_float4(a0.x + a0.y, a1.x + a1.y, a2.x + a2.y, a3.x + a3.y);
        }
        __syncwarp();
    }

    // ---- tile -> global as fp16x4 ----
    __syncthreads();
    const int p0 = blockIdx.x * 24;
    #pragma unroll 1
    for (int t = tid; t < 144 * 24; t += 256) {
        int fq = t / 24, pl = t % 24;
        float4 z = T4[pl * 145 + fq];
        __half2 a = __floats2half2_rn(z.x, z.y);
        __half2 b = __floats2half2_rn(z.z, z.w);
        g_Zh[fq * PP + p0 + pl] = make_uint2(*(uint32*)&a, *(uint32*)&b);
    }
}

// -------------------------------------------------------------------------
// Kernel W12: merged consumer (R15, unchanged). Blocks [0,255): scalar path;
// blocks [255,510): vector path writing RAW v.
// -------------------------------------------------------------------------
#define W1_BIAS 10752
#define W12_SMEM_BYTES ((10752 + 144) * 4)

__global__ void __launch_bounds__(256, 2)
disco_w12(const float* __restrict__ xs,
          const float* __restrict__ W_ss, const float* __restrict__ W_vs,
          const float* __restrict__ W_sv, const float* __restrict__ W_vv,
          const float* __restrict__ bias_s,
          const float* __restrict__ mlp_w1, const float* __restrict__ mlp_b1,
          const float* __restrict__ mlp_w2, const float* __restrict__ mlp_b2,
          const float* __restrict__ gate_w, const float* __restrict__ gate_b,
          float* __restrict__ out) {
    extern __shared__ float sm[];
    const int tid = threadIdx.x;

    if (blockIdx.x < 255) {
        // ================= scalar path =================
        {
            const float4* g = (const float4*)W_ss;
            for (int t = tid; t < 1024; t += 256) { int o = t >> 5, i = t & 31; float4 f = g[t];
                float* b = sm + (i * 4) * 32 + o; b[0] = f.x; b[32] = f.y; b[64] = f.z; b[96] = f.w; }
            g = (const float4*)W_vs;
            for (int t = tid; t < 512; t += 256) { int o = t >> 4, i = t & 15; float4 f = g[t];
                float* b = sm + ((32 + i) * 4) * 32 + o; b[0] = f.x; b[32] = f.y; b[64] = f.z; b[96] = f.w; }
            g = (const float4*)mlp_w1;
            for (int t = tid; t < 512; t += 256) { int j = t >> 3, i4 = t & 7; float4 f = g[t];
                float* b = sm + 6144 + (i4 * 4) * 64 + j; b[0] = f.x; b[64] = f.y; b[128] = f.z; b[192] = f.w; }
            g = (const float4*)mlp_w2;
            for (int t = tid; t < 512; t += 256) { int o = t >> 4, j4 = t & 15; float4 f = g[t];
                float* b = sm + 8192 + (j4 * 4) * 32 + o; b[0] = f.x; b[32] = f.y; b[64] = f.z; b[96] = f.w; }
            g = (const float4*)gate_w;
            for (int t = tid; t < 128; t += 256) { int v = t >> 3, i4 = t & 7; float4 f = g[t];
                float* b = sm + 10240 + (i4 * 4) * 16 + v; b[0] = f.x; b[16] = f.y; b[32] = f.z; b[48] = f.w; }
            if (tid < 32) sm[W1_BIAS + tid]       = bias_s[tid];
            if (tid < 64) sm[W1_BIAS + 32 + tid]  = mlp_b1[tid];
            if (tid < 32) sm[W1_BIAS + 96 + tid]  = mlp_b2[tid];
            if (tid < 16) sm[W1_BIAS + 128 + tid] = gate_b[tid];
        }
        __syncthreads();

        const int p  = blockIdx.x * 256 + tid;
        const int pc = (p < PP) ? p : (PP - 1);

        // ---- phase S ----
        ull acc[16];
        #pragma unroll
        for (int qq = 0; qq < 16; qq++) acc[qq] = *(const ull*)(sm + W1_BIAS + 2 * qq);
        #pragma unroll 4
        for (int r = 0; r < 48; r++) {
            float2 f0, f1;
            h4_to_f4(g_Zh[r * PP + pc], f0, f1);
            ull zk0 = pack2(f0.x, f0.x), zk1 = pack2(f0.y, f0.y);
            ull zk2 = pack2(f1.x, f1.x), zk3 = pack2(f1.y, f1.y);
            const ulonglong2* w0 = (const ulonglong2*)(sm + r * 128);
            #pragma unroll
            for (int q2 = 0; q2 < 8; q2++) {
                ulonglong2 a = w0[q2], b = w0[8 + q2], c = w0[16 + q2], d = w0[24 + q2];
                fma2(acc[2*q2],   a.x, zk0); fma2(acc[2*q2+1], a.y, zk0);
                fma2(acc[2*q2],   b.x, zk1); fma2(acc[2*q2+1], b.y, zk1);
                fma2(acc[2*q2],   c.x, zk2); fma2(acc[2*q2+1], c.y, zk2);
                fma2(acc[2*q2],   d.x, zk3); fma2(acc[2*q2+1], d.y, zk3);
            }
        }
        float s[32];
        #pragma unroll
        for (int qq = 0; qq < 16; qq++) {
            float2 u = unpk(acc[qq]);
            s[2*qq] = gelu_exact(u.x); s[2*qq+1] = gelu_exact(u.y);
        }

        // ---- MLP (j-quarters) ----
        ull soa[16];
        #pragma unroll
        for (int qq = 0; qq < 16; qq++)
            soa[qq] = pack2(s[2*qq] + sm[W1_BIAS + 96 + 2*qq], s[2*qq+1] + sm[W1_BIAS + 97 + 2*qq]);
        #pragma unroll 1
        for (int qt = 0; qt < 4; qt++) {
            ull ha[8];
            #pragma unroll
            for (int qq = 0; qq < 8; qq++) ha[qq] = *(const ull*)(sm + W1_BIAS + 32 + qt * 16 + 2 * qq);
            #pragma unroll
            for (int i = 0; i < 32; i++) {
                ull sx = pack2(s[i], s[i]);
                const ulonglong2* w1r = (const ulonglong2*)(sm + 6144 + i * 64 + qt * 16);
                #pragma unroll
                for (int q2 = 0; q2 < 4; q2++) {
                    ulonglong2 ww = w1r[q2];
                    fma2(ha[2*q2], ww.x, sx); fma2(ha[2*q2+1], ww.y, sx);
                }
            }
            float hh[16];
            #pragma unroll
            for (int qq = 0; qq < 8; qq++) {
                float2 u = unpk(ha[qq]);
                hh[2*qq] = gelu_exact(u.x); hh[2*qq+1] = gelu_exact(u.y);
            }
            #pragma unroll
            for (int jj = 0; jj < 16; jj++) {
                int j = qt * 16 + jj;
                ull hx = pack2(hh[jj], hh[jj]);
                const ulonglong2* w2r = (const ulonglong2*)(sm + 8192 + j * 32);
                #pragma unroll
                for (int q2 = 0; q2 < 8; q2++) {
                    ulonglong2 ww = w2r[q2];
                    fma2(soa[2*q2], ww.x, hx); fma2(soa[2*q2+1], ww.y, hx);
                }
            }
        }
        float so[32];
        #pragma unroll
        for (int qq = 0; qq < 16; qq++) { float2 u = unpk(soa[qq]); so[2*qq] = u.x; so[2*qq+1] = u.y; }

        // ---- gate ----
        ull ga[8];
        #pragma unroll
        for (int qq = 0; qq < 8; qq++) ga[qq] = *(const ull*)(sm + W1_BIAS + 128 + 2 * qq);
        #pragma unroll
        for (int i = 0; i < 32; i++) {
            ull sx = pack2(so[i], so[i]);
            const ulonglong2* gr = (const ulonglong2*)(sm + 10240 + i * 16);
            #pragma unroll
            for (int q2 = 0; q2 < 4; q2++) {
                ulonglong2 ww = gr[q2];
                fma2(ga[2*q2], ww.x, sx); fma2(ga[2*q2+1], ww.y, sx);
            }
        }

        if (p < PP) {
            #pragma unroll
            for (int o = 0; o < 32; o++) out[o * PP + p] = xs[o * PP + p] + so[o];
            #pragma unroll
            for (int qq = 0; qq < 8; qq++) {
                float2 u = unpk(ga[qq]);
                g_gte[(2*qq) * PP + p]   = 1.f + u.x;
                g_gte[(2*qq+1) * PP + p] = 1.f + u.y;
            }
        }
    } else {
        // ================= vector path (raw v, no gate) =================
        {
            const float4* g = (const float4*)W_sv;
            for (int t = tid; t < 512; t += 256) { int o = t >> 5, i = t & 31; float4 f = g[t];
                float* b = sm + (i * 4) * 16 + o; b[0] = f.x; b[16] = f.y; b[32] = f.z; b[48] = f.w; }
            g = (const float4*)W_vv;
            for (int t = tid; t < 256; t += 256) { int o = t >> 4, i = t & 15; float4 f = g[t];
                float* b = sm + ((32 + i) * 4) * 16 + o; b[0] = f.x; b[16] = f.y; b[32] = f.z; b[48] = f.w; }
        }
        __syncthreads();

        const int p  = (blockIdx.x - 255) * 256 + tid;
        const int pc = (p < PP) ? p : (PP - 1);

        ull vx[8], vy[8];
        #pragma unroll
        for (int qq = 0; qq < 8; qq++) { vx[qq] = 0ULL; vy[qq] = 0ULL; }
        #pragma unroll 4
        for (int r = 0; r < 32; r++) {
            float2 e0, e1, g0, g1;
            h4_to_f4(g_Zh[(48 + r) * PP + pc], e0, e1);
            h4_to_f4(g_Zh[(80 + r) * PP + pc], g0, g1);
            ull a0 = pack2(e0.x, e0.x), a1 = pack2(e0.y, e0.y), a2 = pack2(e1.x, e1.x), a3 = pack2(e1.y, e1.y);
            ull b0 = pack2(g0.x, g0.x), b1 = pack2(g0.y, g0.y), b2 = pack2(g1.x, g1.x), b3 = pack2(g1.y, g1.y);
            const ulonglong2* wv = (const ulonglong2*)(sm + r * 64);
            #pragma unroll
            for (int q2 = 0; q2 < 4; q2++) {
                ulonglong2 wa = wv[q2], wb = wv[4 + q2], wc = wv[8 + q2], wd = wv[12 + q2];
                fma2(vx[2*q2], wa.x, a0); fma2(vx[2*q2+1], wa.y, a0);
                fma2(vy[2*q2], wa.x, b0); fma2(vy[2*q2+1], wa.y, b0);
                fma2(vx[2*q2], wb.x, a1); fma2(vx[2*q2+1], wb.y, a1);
                fma2(vy[2*q2], wb.x, b1); fma2(vy[2*q2+1], wb.y, b1);
                fma2(vx[2*q2], wc.x, a2); fma2(vx[2*q2+1], wc.y, a2);
                fma2(vy[2*q2], wc.x, b2); fma2(vy[2*q2+1], wc.y, b2);
                fma2(vx[2*q2], wd.x, a3); fma2(vx[2*q2+1], wd.y, a3);
                fma2(vy[2*q2], wd.x, b3); fma2(vy[2*q2+1], wd.y, b3);
            }
        }
        #pragma unroll 4
        for (int r = 0; r < 16; r++) {
            float2 e0, e1, g0, g1;
            h4_to_f4(g_Zh[(112 + r) * PP + pc], e0, e1);
            h4_to_f4(g_Zh[(128 + r) * PP + pc], g0, g1);
            ull a0 = pack2(e0.x, e0.x), a1 = pack2(e0.y, e0.y), a2 = pack2(e1.x, e1.x), a3 = pack2(e1.y, e1.y);
            ull b0 = pack2(g0.x, g0.x), b1 = pack2(g0.y, g0.y), b2 = pack2(g1.x, g1.x), b3 = pack2(g1.y, g1.y);
            const ulonglong2* wv = (const ulonglong2*)(sm + (32 + r) * 64);
            #pragma unroll
            for (int q2 = 0; q2 < 4; q2++) {
                ulonglong2 wa = wv[q2], wb = wv[4 + q2], wc = wv[8 + q2], wd = wv[12 + q2];
                fma2(vx[2*q2], wa.x, a0); fma2(vx[2*q2+1], wa.y, a0);
                fma2(vy[2*q2], wa.x, b0); fma2(vy[2*q2+1], wa.y, b0);
                fma2(vx[2*q2], wb.x, a1); fma2(vx[2*q2+1], wb.y, a1);
                fma2(vy[2*q2], wb.x, b1); fma2(vy[2*q2+1], wb.y, b1);
                fma2(vx[2*q2], wc.x, a2); fma2(vx[2*q2+1], wc.y, a2);
                fma2(vy[2*q2], wc.x, b2); fma2(vy[2*q2+1], wc.y, b2);
                fma2(vx[2*q2], wd.x, a3); fma2(vx[2*q2+1], wd.y, a3);
                fma2(vy[2*q2], wd.x, b3); fma2(vy[2*q2+1], wd.y, b3);
            }
        }
        if (p < PP) {
            float2* outv = (float2*)(out + 32 * PP);
            #pragma unroll
            for (int qq = 0; qq < 8; qq++) {
                float2 ux = unpk(vx[qq]), uy = unpk(vy[qq]);
                int o0 = 2 * qq, o1 = 2 * qq + 1;
                outv[o0 * PP + p] = make_float2(ux.x, uy.x);   // raw v
                outv[o1 * PP + p] = make_float2(ux.y, uy.y);
            }
        }
    }
}

// -------------------------------------------------------------------------
// Kernel W3: combiner. out_v = xv + gte * raw_v
// -------------------------------------------------------------------------
__global__ void disco_w3(const float* __restrict__ xv, float* __restrict__ out) {
    const int p = blockIdx.x * 256 + threadIdx.x;
    const int v = blockIdx.y;
    if (p < PP) {
        float g = g_gte[v * PP + p];
        float2* outv = (float2*)(out + 32 * PP);
        const float2* xv2 = (const float2*)xv;
        float2 raw = outv[v * PP + p];
        float2 b   = xv2[v * PP + p];
        outv[v * PP + p] = make_float2(b.x + g * raw.x, b.y + g * raw.y);
    }
}

extern "C" void kernel_launch(void* const* d_in, const int* in_sizes, int n_in,
                              void* d_out, int out_size) {
    const bool dictOrder = (in_sizes[2] == PP * 16);
    const float* xs = (const float*)d_in[0];
    const float* xv = (const float*)d_in[1];
    const int base = dictOrder ? 3 : 2;
    const float* pss  = (const float*)d_in[base + 0];
    const float* psv  = (const float*)d_in[base + 1];
    const float* pvs  = (const float*)d_in[base + 2];
    const float* pvv  = (const float*)d_in[base + 3];
    const float* wss  = (const float*)d_in[base + 4];
    const float* wvs  = (const float*)d_in[base + 5];
    const float* wsv  = (const float*)d_in[base + 6];
    const float* wvv  = (const float*)d_in[base + 7];
    const float* bs   = (const float*)d_in[base + 8];
    const float* w1   = (const float*)d_in[base + 9];
    const float* b1   = (const float*)d_in[base + 10];
    const float* w2   = (const float*)d_in[base + 11];
    const float* b2   = (const float*)d_in[base + 12];
    const float* gw   = (const float*)d_in[base + 13];
    const float* gb   = (const float*)d_in[base + 14];
    const int*   idx  = (const int*)(dictOrder ? d_in[2] : d_in[17]);

    cudaFuncSetAttribute(disco_z,   cudaFuncAttributeMaxDynamicSharedMemorySize, A_SMEM_BYTES);
    cudaFuncSetAttribute(disco_w12, cudaFuncAttributeMaxDynamicSharedMemorySize, W12_SMEM_BYTES);

    float* out = (float*)d_out;
    dim3 tb(32, 8);
    transpose_x<<<dim3((PP + 31) / 32, 2), tb>>>(xs, xv);
    disco_z<<<2715, 256, A_SMEM_BYTES>>>(idx, pss, psv, pvs, pvv);
    disco_w12<<<510, 256, W12_SMEM_BYTES>>>(xs, wss, wvs, wsv, wvv, bs,
                                            w1, b1, w2, b2, gw, gb, out);
    disco_w3<<<dim3(255, 16), 256>>>(xv, out);
}